// round 1
// baseline (speedup 1.0000x reference)
#include <cuda_runtime.h>
#include <math.h>

#define B_  8
#define N_  4096
#define L_  4096
#define GC_ 32
#define IC_ 256

// Scratch (static device globals — allocation-free per harness rules)
__device__ float g_Q [B_*N_*GC_];   // [b][n][o]
__device__ float g_KT[B_*L_*GC_];   // [b][l][o]
__device__ float g_VT[B_*L_*GC_];   // [b][l][o]
__device__ float g_M [B_*L_];       // per-(b,l) max over n of scaled scores
__device__ float g_D [B_*L_];       // per-(b,l) sum exp

#define SCALE 0.17677669529663687f  // 1/sqrt(32)

// ---------------------------------------------------------------------------
// Kernel 1: Q[b,n,o] = sum_c Wq[o,c]*graph[b,n,c] + bq[o]
// grid = B * (N/64), block = 256
// ---------------------------------------------------------------------------
__global__ __launch_bounds__(256) void k_proj_q(
    const float* __restrict__ graph, const float* __restrict__ Wq,
    const float* __restrict__ bq)
{
    __shared__ float WqS[GC_*33];
    __shared__ float gS[64*GC_];
    int b  = blockIdx.x >> 6;
    int n0 = (blockIdx.x & 63) * 64;
    int tid = threadIdx.x;

    for (int i = tid; i < GC_*GC_; i += 256)
        WqS[(i>>5)*33 + (i&31)] = Wq[i];
    const float* gp = graph + ((long)b*N_ + n0)*GC_;
    for (int i = tid; i < 64*GC_; i += 256) gS[i] = gp[i];
    __syncthreads();

    int o = tid & 31, nb = tid >> 5;
    float bias = bq[o];
    #pragma unroll
    for (int j = 0; j < 8; j++) {
        int n = nb + j*8;
        float acc = bias;
        #pragma unroll
        for (int c = 0; c < 32; c++) acc += WqS[o*33+c] * gS[n*32+c];
        g_Q[((long)b*N_ + n0 + n)*GC_ + o] = acc;
    }
}

// ---------------------------------------------------------------------------
// Kernel 2: K^T[b,l,o], V^T[b,l,o] from img[b,c,l] (1x1 conv, C=256)
// grid = B * (L/64), block = 256. Thread tile: 4 l x 4 o, K or V half.
// ---------------------------------------------------------------------------
__global__ __launch_bounds__(256) void k_proj_kv(
    const float* __restrict__ img,
    const float* __restrict__ Wk, const float* __restrict__ bk,
    const float* __restrict__ Wv, const float* __restrict__ bv)
{
    __shared__ float imgS[32*64];
    __shared__ float WkS[32*33];
    __shared__ float WvS[32*33];
    int b  = blockIdx.x >> 6;
    int l0 = (blockIdx.x & 63) * 64;
    int tid = threadIdx.x;
    int lg = tid >> 4;          // 0..15 -> 4 l's each
    int og = tid & 15;          // 0..7 K, 8..15 V
    bool isK = og < 8;
    int obase = (og & 7) * 4;

    float acc[4][4];            // [jo][jl]
    #pragma unroll
    for (int a = 0; a < 4; a++)
        #pragma unroll
        for (int c = 0; c < 4; c++) acc[a][c] = 0.f;

    for (int c0 = 0; c0 < IC_; c0 += 32) {
        __syncthreads();
        for (int i = tid; i < 32*64; i += 256) {
            int ci = i >> 6, li = i & 63;
            imgS[i] = img[((long)b*IC_ + c0 + ci)*L_ + l0 + li];
        }
        for (int i = tid; i < 32*32; i += 256) {
            int o = i >> 5, ci = i & 31;
            WkS[o*33+ci] = Wk[o*IC_ + c0 + ci];
            WvS[o*33+ci] = Wv[o*IC_ + c0 + ci];
        }
        __syncthreads();
        const float* Ws = isK ? WkS : WvS;
        #pragma unroll
        for (int ci = 0; ci < 32; ci++) {
            float4 iv = *(const float4*)&imgS[ci*64 + lg*4];
            #pragma unroll
            for (int jo = 0; jo < 4; jo++) {
                float w = Ws[(obase+jo)*33 + ci];
                acc[jo][0] += w*iv.x; acc[jo][1] += w*iv.y;
                acc[jo][2] += w*iv.z; acc[jo][3] += w*iv.w;
            }
        }
    }
    float* dst = isK ? g_KT : g_VT;
    const float* bias = isK ? bk : bv;
    #pragma unroll
    for (int jo = 0; jo < 4; jo++) {
        float bs = bias[obase+jo];
        #pragma unroll
        for (int jl = 0; jl < 4; jl++)
            dst[((long)b*L_ + l0 + lg*4 + jl)*GC_ + obase + jo] = acc[jo][jl] + bs;
    }
}

// ---------------------------------------------------------------------------
// Kernel 3: per-(b,l) online softmax stats over n.
// Block tile: 128 l, stream n in chunks of 128. 16x16 threads, 8x8 reg tile
// (strided: row = ty+16i, col = tx+16j).
// grid = B * (L/128) = 256
// ---------------------------------------------------------------------------
__global__ __launch_bounds__(256) void k_stats()
{
    __shared__ float KTs[128*33];
    __shared__ float Qs [128*33];
    int b  = blockIdx.x >> 5;
    int l0 = (blockIdx.x & 31) * 128;
    int tid = threadIdx.x;
    int ty = tid >> 4, tx = tid & 15;

    const float* kp = g_KT + ((long)b*L_ + l0)*GC_;
    for (int i = tid; i < 128*32; i += 256)
        KTs[(i>>5)*33 + (i&31)] = kp[i];

    float m[8], d[8];
    #pragma unroll
    for (int i = 0; i < 8; i++) { m[i] = -1e30f; d[i] = 0.f; }

    for (int nc = 0; nc < N_/128; nc++) {
        __syncthreads();
        const float* qp = g_Q + ((long)b*N_ + nc*128)*GC_;
        for (int i = tid; i < 128*32; i += 256)
            Qs[(i>>5)*33 + (i&31)] = qp[i];
        __syncthreads();

        float s[8][8];
        #pragma unroll
        for (int i = 0; i < 8; i++)
            #pragma unroll
            for (int j = 0; j < 8; j++) s[i][j] = 0.f;

        #pragma unroll
        for (int k = 0; k < 32; k++) {
            float a[8], bb[8];
            #pragma unroll
            for (int i = 0; i < 8; i++) a[i]  = KTs[(ty+16*i)*33 + k];
            #pragma unroll
            for (int j = 0; j < 8; j++) bb[j] = Qs [(tx+16*j)*33 + k];
            #pragma unroll
            for (int i = 0; i < 8; i++)
                #pragma unroll
                for (int j = 0; j < 8; j++) s[i][j] += a[i]*bb[j];
        }
        #pragma unroll
        for (int i = 0; i < 8; i++) {
            float rowmax = s[i][0];
            #pragma unroll
            for (int j = 1; j < 8; j++) rowmax = fmaxf(rowmax, s[i][j]);
            rowmax *= SCALE;
            float mn = fmaxf(m[i], rowmax);
            float sum = 0.f;
            #pragma unroll
            for (int j = 0; j < 8; j++) sum += __expf(s[i][j]*SCALE - mn);
            d[i] = d[i]*__expf(m[i] - mn) + sum;
            m[i] = mn;
        }
    }
    // reduce over the 16 tx threads (xor within 16-lane half-warp)
    #pragma unroll
    for (int i = 0; i < 8; i++) {
        float mi = m[i], di = d[i];
        #pragma unroll
        for (int off = 8; off; off >>= 1) {
            float m2 = __shfl_xor_sync(0xffffffffu, mi, off);
            float d2 = __shfl_xor_sync(0xffffffffu, di, off);
            float mn = fmaxf(mi, m2);
            di = di*__expf(mi - mn) + d2*__expf(m2 - mn);
            mi = mn;
        }
        if (tx == 0) {
            g_M[(long)b*L_ + l0 + ty + 16*i] = mi;
            g_D[(long)b*L_ + l0 + ty + 16*i] = di;
        }
    }
}

// ---------------------------------------------------------------------------
// Kernel 4: fused  p = exp(s-m[l])/D[l];  msg[c,n] += p * V^T[l,c];
//           out = graph + Wc*msg + bc.
// Block: 128 n, stream l in chunks of 128. Dynamic SMEM (~125 KB).
// grid = B * (N/128) = 256
// ---------------------------------------------------------------------------
#define SM_QS   0
#define SM_KTS  4224
#define SM_VS   8448     // pitch 36 (float4-aligned)
#define SM_MV   13056
#define SM_DI   13184
#define SM_WC   13312
#define SM_BC   14368
#define SM_P    14400    // 128 x pitch 132
#define SM4_FLOATS (14400 + 128*132)

__global__ __launch_bounds__(256) void k_final(
    const float* __restrict__ graph,
    const float* __restrict__ Wc, const float* __restrict__ bc,
    float* __restrict__ out)
{
    extern __shared__ float sm[];
    float* Qs   = sm + SM_QS;
    float* KTs  = sm + SM_KTS;
    float* Vs   = sm + SM_VS;
    float* Mv   = sm + SM_MV;
    float* Dinv = sm + SM_DI;
    float* WcS  = sm + SM_WC;
    float* bcS  = sm + SM_BC;
    float* P    = sm + SM_P;

    int b  = blockIdx.x >> 5;
    int n0 = (blockIdx.x & 31) * 128;
    int tid = threadIdx.x;
    int ty = tid >> 4, tx = tid & 15;
    int ng = tid >> 3, cg = tid & 7;   // phase-B: 4 n x 4 c per thread

    const float* qp = g_Q + ((long)b*N_ + n0)*GC_;
    for (int i = tid; i < 128*32; i += 256)
        Qs[(i>>5)*33 + (i&31)] = qp[i];
    for (int i = tid; i < 32*32; i += 256)
        WcS[(i>>5)*33 + (i&31)] = Wc[i];
    if (tid < 32) bcS[tid] = bc[tid];

    float acc[4][4];
    #pragma unroll
    for (int a = 0; a < 4; a++)
        #pragma unroll
        for (int c = 0; c < 4; c++) acc[a][c] = 0.f;

    for (int lc = 0; lc < L_/128; lc++) {
        __syncthreads();
        const float* kp = g_KT + ((long)b*L_ + lc*128)*GC_;
        const float* vp = g_VT + ((long)b*L_ + lc*128)*GC_;
        for (int i = tid; i < 128*32; i += 256) {
            KTs[(i>>5)*33 + (i&31)] = kp[i];
            Vs [(i>>5)*36 + (i&31)] = vp[i];
        }
        if (tid < 128) {
            Mv[tid]   = g_M[(long)b*L_ + lc*128 + tid];
            Dinv[tid] = 1.0f / g_D[(long)b*L_ + lc*128 + tid];
        }
        __syncthreads();

        // Phase A: scores + exp -> P
        float s[8][8];
        #pragma unroll
        for (int i = 0; i < 8; i++)
            #pragma unroll
            for (int j = 0; j < 8; j++) s[i][j] = 0.f;
        #pragma unroll
        for (int k = 0; k < 32; k++) {
            float a[8], bb[8];
            #pragma unroll
            for (int i = 0; i < 8; i++) a[i]  = KTs[(ty+16*i)*33 + k];
            #pragma unroll
            for (int j = 0; j < 8; j++) bb[j] = Qs [(tx+16*j)*33 + k];
            #pragma unroll
            for (int i = 0; i < 8; i++)
                #pragma unroll
                for (int j = 0; j < 8; j++) s[i][j] += a[i]*bb[j];
        }
        #pragma unroll
        for (int i = 0; i < 8; i++) {
            int l = ty + 16*i;
            float mi = Mv[l], di = Dinv[l];
            #pragma unroll
            for (int j = 0; j < 8; j++)
                P[l*132 + tx + 16*j] = __expf(s[i][j]*SCALE - mi) * di;
        }
        __syncthreads();

        // Phase B: acc[n][c] += sum_l P[l][n] * V^T[l][c]
        #pragma unroll 4
        for (int l = 0; l < 128; l++) {
            float4 pv = *(const float4*)&P [l*132 + ng*4];
            float4 vv = *(const float4*)&Vs[l*36  + cg*4];
            acc[0][0] += pv.x*vv.x; acc[0][1] += pv.x*vv.y; acc[0][2] += pv.x*vv.z; acc[0][3] += pv.x*vv.w;
            acc[1][0] += pv.y*vv.x; acc[1][1] += pv.y*vv.y; acc[1][2] += pv.y*vv.z; acc[1][3] += pv.y*vv.w;
            acc[2][0] += pv.z*vv.x; acc[2][1] += pv.z*vv.y; acc[2][2] += pv.z*vv.z; acc[2][3] += pv.z*vv.w;
            acc[3][0] += pv.w*vv.x; acc[3][1] += pv.w*vv.y; acc[3][2] += pv.w*vv.z; acc[3][3] += pv.w*vv.w;
        }
    }

    // Epilogue: msg -> smem, then out = graph + Wc*msg + bc
    __syncthreads();
    float* msgS = P;   // reuse: msg[n][c], pitch 33
    #pragma unroll
    for (int a = 0; a < 4; a++)
        #pragma unroll
        for (int c = 0; c < 4; c++)
            msgS[(ng*4 + a)*33 + cg*4 + c] = acc[a][c];
    __syncthreads();

    int o = tid & 31, nb = tid >> 5;
    const float* gp = graph + ((long)b*N_ + n0)*GC_;
    float bias = bcS[o];
    for (int j = 0; j < 16; j++) {
        int n = nb + 8*j;
        float r = bias;
        #pragma unroll
        for (int c = 0; c < 32; c++) r += WcS[o*33+c] * msgS[n*33+c];
        out[((long)b*N_ + n0 + n)*GC_ + o] = gp[n*GC_ + o] + r;
    }
}

// ---------------------------------------------------------------------------
extern "C" void kernel_launch(void* const* d_in, const int* in_sizes, int n_in,
                              void* d_out, int out_size)
{
    const float* graph = (const float*)d_in[0];
    const float* img   = (const float*)d_in[1];
    const float* Wq    = (const float*)d_in[2];
    const float* bq    = (const float*)d_in[3];
    const float* Wk    = (const float*)d_in[4];
    const float* bk    = (const float*)d_in[5];
    const float* Wv    = (const float*)d_in[6];
    const float* bv    = (const float*)d_in[7];
    const float* Wc    = (const float*)d_in[8];
    const float* bc    = (const float*)d_in[9];
    float* out = (float*)d_out;

    static int smem_set = 0;
    size_t smem4 = SM4_FLOATS * sizeof(float);
    if (!smem_set) {
        cudaFuncSetAttribute(k_final, cudaFuncAttributeMaxDynamicSharedMemorySize,
                             (int)smem4);
        smem_set = 1;
    }

    k_proj_q <<<B_*(N_/64), 256>>>(graph, Wq, bq);
    k_proj_kv<<<B_*(L_/64), 256>>>(img, Wk, bk, Wv, bv);
    k_stats  <<<B_*(L_/128), 256>>>();
    k_final  <<<B_*(N_/128), 256, smem4>>>(graph, Wc, bc, out);
}

// round 3
// speedup vs baseline: 3.6471x; 3.6471x over previous
#include <cuda_runtime.h>
#include <cstdint>

#define B_  8
#define N_  4096
#define L_  4096
#define GC_ 32
#define IC_ 256

__device__ float g_Q [B_*N_*GC_];   // [b][n][32], prescaled by SCALE*LOG2E
__device__ float g_KT[B_*L_*GC_];   // [b][l][32]
__device__ float g_VT[B_*L_*GC_];   // [b][l][32]
__device__ float g_DI[B_*L_];       // 1 / sum_n exp(s)

#define QSCALE 0.2550668292560464f  // (1/sqrt(32)) * log2(e)

// ===========================================================================
// helpers
// ===========================================================================
__device__ __forceinline__ uint32_t f2tf(float f) {
    uint32_t u;
    asm("cvt.rna.tf32.f32 %0, %1;" : "=r"(u) : "f"(f));
    return u;
}
__device__ __forceinline__ float ex2f(float x) {
    float y;
    asm("ex2.approx.f32 %0, %1;" : "=f"(y) : "f"(x));
    return y;
}
__device__ __forceinline__ void mma_tf32(float c[4], const uint32_t a[4],
                                         uint32_t b0, uint32_t b1) {
    asm volatile("mma.sync.aligned.m16n8k8.row.col.f32.tf32.tf32.f32 "
        "{%0,%1,%2,%3}, {%4,%5,%6,%7}, {%8,%9}, {%0,%1,%2,%3};"
        : "+f"(c[0]), "+f"(c[1]), "+f"(c[2]), "+f"(c[3])
        : "r"(a[0]), "r"(a[1]), "r"(a[2]), "r"(a[3]), "r"(b0), "r"(b1));
}

// ===========================================================================
// Kernel 1: Q projection, folds QSCALE
// ===========================================================================
__global__ __launch_bounds__(256) void k_proj_q(
    const float* __restrict__ graph, const float* __restrict__ Wq,
    const float* __restrict__ bq)
{
    __shared__ float WqS[GC_*33];
    __shared__ float gS[64*GC_];
    int b  = blockIdx.x >> 6;
    int n0 = (blockIdx.x & 63) * 64;
    int tid = threadIdx.x;

    for (int i = tid; i < GC_*GC_; i += 256)
        WqS[(i>>5)*33 + (i&31)] = Wq[i];
    const float* gp = graph + ((long)b*N_ + n0)*GC_;
    for (int i = tid; i < 64*GC_; i += 256) gS[i] = gp[i];
    __syncthreads();

    int o = tid & 31, nb = tid >> 5;
    float bias = bq[o];
    #pragma unroll
    for (int j = 0; j < 8; j++) {
        int n = nb + j*8;
        float acc = bias;
        #pragma unroll
        for (int c = 0; c < 32; c++) acc += WqS[o*33+c] * gS[n*32+c];
        g_Q[((long)b*N_ + n0 + n)*GC_ + o] = acc * QSCALE;
    }
}

// ===========================================================================
// Kernel 2: K/V projection
// ===========================================================================
__global__ __launch_bounds__(256) void k_proj_kv(
    const float* __restrict__ img,
    const float* __restrict__ Wk, const float* __restrict__ bk,
    const float* __restrict__ Wv, const float* __restrict__ bv)
{
    __shared__ float imgS[32*64];
    __shared__ float WkS[32*33];
    __shared__ float WvS[32*33];
    int b  = blockIdx.x >> 6;
    int l0 = (blockIdx.x & 63) * 64;
    int tid = threadIdx.x;
    int lg = tid >> 4;
    int og = tid & 15;
    bool isK = og < 8;
    int obase = (og & 7) * 4;

    float acc[4][4];
    #pragma unroll
    for (int a = 0; a < 4; a++)
        #pragma unroll
        for (int c = 0; c < 4; c++) acc[a][c] = 0.f;

    for (int c0 = 0; c0 < IC_; c0 += 32) {
        __syncthreads();
        for (int i = tid; i < 32*64; i += 256) {
            int ci = i >> 6, li = i & 63;
            imgS[i] = img[((long)b*IC_ + c0 + ci)*L_ + l0 + li];
        }
        for (int i = tid; i < 32*32; i += 256) {
            int o = i >> 5, ci = i & 31;
            WkS[o*33+ci] = Wk[o*IC_ + c0 + ci];
            WvS[o*33+ci] = Wv[o*IC_ + c0 + ci];
        }
        __syncthreads();
        const float* Ws = isK ? WkS : WvS;
        #pragma unroll
        for (int ci = 0; ci < 32; ci++) {
            float4 iv = *(const float4*)&imgS[ci*64 + lg*4];
            #pragma unroll
            for (int jo = 0; jo < 4; jo++) {
                float w = Ws[(obase+jo)*33 + ci];
                acc[jo][0] += w*iv.x; acc[jo][1] += w*iv.y;
                acc[jo][2] += w*iv.z; acc[jo][3] += w*iv.w;
            }
        }
    }
    float* dst = isK ? g_KT : g_VT;
    const float* bias = isK ? bk : bv;
    #pragma unroll
    for (int jo = 0; jo < 4; jo++) {
        float bs = bias[obase+jo];
        #pragma unroll
        for (int jl = 0; jl < 4; jl++)
            dst[((long)b*L_ + l0 + lg*4 + jl)*GC_ + obase + jo] = acc[jo][jl] + bs;
    }
}

// ===========================================================================
// Kernel 3: stats via mma.sync tf32.
// Sᵀ[l,n] = K·Qᵀ; D[l] = Σ_n exp2(s). Warp owns 16 l-rows.
// Qs layout: [n][pos(k)] with pos(k) = (k&3)*8 + (k>>2), pitch 36.
// ===========================================================================
__global__ __launch_bounds__(256, 2) void k_stats_mma()
{
    __shared__ __align__(16) uint32_t Qs[128*36];
    int tid = threadIdx.x, w = tid >> 5, lane = tid & 31;
    int q = lane & 3, g = lane >> 2;
    int b = blockIdx.x >> 5, l0 = (blockIdx.x & 31) * 128;

    // A frags = K rows (persistent)
    uint32_t A[4][4];
    const float* kp = g_KT + ((long)b*L_ + l0 + w*16)*32;
    #pragma unroll
    for (int kk = 0; kk < 4; kk++) {
        A[kk][0] = f2tf(kp[ g   *32 + 8*kk + q    ]);
        A[kk][1] = f2tf(kp[(g+8)*32 + 8*kk + q    ]);
        A[kk][2] = f2tf(kp[ g   *32 + 8*kk + q + 4]);
        A[kk][3] = f2tf(kp[(g+8)*32 + 8*kk + q + 4]);
    }

    float d0 = 0.f, d1 = 0.f;
    for (int nc = 0; nc < 32; nc++) {
        const float4* qp = (const float4*)(g_Q + ((long)b*N_ + nc*128)*32);
        #pragma unroll
        for (int it = 0; it < 4; it++) {
            int i = tid + it*256;          // 1024 float4
            int r = i >> 3, t = i & 7;
            float4 v = qp[i];
            Qs[r*36 +  0 + t] = f2tf(v.x);
            Qs[r*36 +  8 + t] = f2tf(v.y);
            Qs[r*36 + 16 + t] = f2tf(v.z);
            Qs[r*36 + 24 + t] = f2tf(v.w);
        }
        __syncthreads();
        #pragma unroll 4
        for (int j = 0; j < 16; j++) {
            const uint32_t* bp = &Qs[(g + 8*j)*36 + q*8];
            uint4 f0 = *(const uint4*)bp;
            uint4 f1 = *(const uint4*)(bp + 4);
            float c[4] = {0.f, 0.f, 0.f, 0.f};
            mma_tf32(c, A[0], f0.x, f0.y);
            mma_tf32(c, A[1], f0.z, f0.w);
            mma_tf32(c, A[2], f1.x, f1.y);
            mma_tf32(c, A[3], f1.z, f1.w);
            d0 += ex2f(c[0]) + ex2f(c[1]);
            d1 += ex2f(c[2]) + ex2f(c[3]);
        }
        __syncthreads();
    }
    d0 += __shfl_xor_sync(~0u, d0, 1); d0 += __shfl_xor_sync(~0u, d0, 2);
    d1 += __shfl_xor_sync(~0u, d1, 1); d1 += __shfl_xor_sync(~0u, d1, 2);
    if (q == 0) {
        g_DI[(long)b*L_ + l0 + w*16 + g    ] = 1.0f / d0;
        g_DI[(long)b*L_ + l0 + w*16 + g + 8] = 1.0f / d1;
    }
}

// ===========================================================================
// Kernel 4: final.
//   GEMM1 S[n,l]=Q·Kᵀ -> ex2 -> shfl-transpose -> GEMM2 msg += P·V'
//   (Dinv folded into V'), epilogue GEMM3 out = graph + bc + msg·Wcᵀ.
// Ks:  [l][pos(k)]            pitch 36
// Vs:  [c][(l&3)*40 + (l>>2)] pitch 162 (conflict-free float2 B loads)
// Wcs: [o][pos(c)]            pitch 36
// ===========================================================================
__global__ __launch_bounds__(256, 2) void k_final_mma(
    const float* __restrict__ graph, const float* __restrict__ Wc,
    const float* __restrict__ bc, float* __restrict__ out)
{
    __shared__ __align__(16) uint32_t Ks[128*36];
    __shared__ __align__(16) uint32_t Vs[32*162];
    __shared__ __align__(16) uint32_t Wcs[32*36];
    int tid = threadIdx.x, w = tid >> 5, lane = tid & 31;
    int q = lane & 3, g = lane >> 2;
    int b = blockIdx.x >> 5, n0 = (blockIdx.x & 31) * 128;

    // A frags = Q rows (persistent; prescaled)
    uint32_t A[4][4];
    const float* qp = g_Q + ((long)b*N_ + n0 + w*16)*32;
    #pragma unroll
    for (int kk = 0; kk < 4; kk++) {
        A[kk][0] = f2tf(qp[ g   *32 + 8*kk + q    ]);
        A[kk][1] = f2tf(qp[(g+8)*32 + 8*kk + q    ]);
        A[kk][2] = f2tf(qp[ g   *32 + 8*kk + q + 4]);
        A[kk][3] = f2tf(qp[(g+8)*32 + 8*kk + q + 4]);
    }
    // Wc (tf32, permuted)
    for (int i = tid; i < 32*8; i += 256) {
        int o = i >> 3, t = i & 7;
        float4 v = ((const float4*)Wc)[i];
        Wcs[o*36 +  0 + t] = f2tf(v.x);
        Wcs[o*36 +  8 + t] = f2tf(v.y);
        Wcs[o*36 + 16 + t] = f2tf(v.z);
        Wcs[o*36 + 24 + t] = f2tf(v.w);
    }

    float mc[4][4];
    #pragma unroll
    for (int cf = 0; cf < 4; cf++)
        #pragma unroll
        for (int x = 0; x < 4; x++) mc[cf][x] = 0.f;

    int srcA = (lane & ~3) | (q >> 1);
    int srcB = srcA + 2;

    for (int lc = 0; lc < 32; lc++) {
        const float4* kp = (const float4*)(g_KT + ((long)b*L_ + lc*128)*32);
        #pragma unroll
        for (int it = 0; it < 4; it++) {
            int i = tid + it*256;
            int r = i >> 3, t = i & 7;
            float4 v = kp[i];
            Ks[r*36 +  0 + t] = f2tf(v.x);
            Ks[r*36 +  8 + t] = f2tf(v.y);
            Ks[r*36 + 16 + t] = f2tf(v.z);
            Ks[r*36 + 24 + t] = f2tf(v.w);
        }
        {
            const float* vp = g_VT + ((long)b*L_ + lc*128)*32;
            const float* dp = g_DI + (long)b*L_ + lc*128;
            #pragma unroll
            for (int it = 0; it < 16; it++) {
                int i = tid + it*256;
                int l = i >> 5, c = i & 31;
                Vs[c*162 + (l&3)*40 + (l>>2)] = f2tf(vp[i] * dp[l]);
            }
        }
        __syncthreads();
        #pragma unroll 4
        for (int j = 0; j < 16; j++) {
            const uint32_t* bp = &Ks[(g + 8*j)*36 + q*8];
            uint4 f0 = *(const uint4*)bp;
            uint4 f1 = *(const uint4*)(bp + 4);
            float c[4] = {0.f, 0.f, 0.f, 0.f};
            mma_tf32(c, A[0], f0.x, f0.y);
            mma_tf32(c, A[1], f0.z, f0.w);
            mma_tf32(c, A[2], f1.x, f1.y);
            mma_tf32(c, A[3], f1.z, f1.w);
            float e0 = ex2f(c[0]), e1 = ex2f(c[1]);
            float e2 = ex2f(c[2]), e3 = ex2f(c[3]);
            // C-frag (n x l) -> A-frag (m16 x k8) transpose within quads
            float x0 = __shfl_sync(~0u, e0, srcA), x1 = __shfl_sync(~0u, e1, srcA);
            float y0 = __shfl_sync(~0u, e0, srcB), y1 = __shfl_sync(~0u, e1, srcB);
            float x2 = __shfl_sync(~0u, e2, srcA), x3 = __shfl_sync(~0u, e3, srcA);
            float y2 = __shfl_sync(~0u, e2, srcB), y3 = __shfl_sync(~0u, e3, srcB);
            uint32_t A2[4];
            A2[0] = f2tf((q & 1) ? x1 : x0);
            A2[1] = f2tf((q & 1) ? x3 : x2);
            A2[2] = f2tf((q & 1) ? y1 : y0);
            A2[3] = f2tf((q & 1) ? y3 : y2);
            #pragma unroll
            for (int cf = 0; cf < 4; cf++) {
                uint2 bv = *(const uint2*)&Vs[(g + 8*cf)*162 + q*40 + 2*j];
                mma_tf32(mc[cf], A2, bv.x, bv.y);
            }
        }
        __syncthreads();
    }

    // Epilogue GEMM3: out = graph + bc + msg · Wcᵀ
    uint32_t A3[4][4];
    #pragma unroll
    for (int kk = 0; kk < 4; kk++) {
        float e0 = mc[kk][0], e1 = mc[kk][1], e2 = mc[kk][2], e3 = mc[kk][3];
        float x0 = __shfl_sync(~0u, e0, srcA), x1 = __shfl_sync(~0u, e1, srcA);
        float y0 = __shfl_sync(~0u, e0, srcB), y1 = __shfl_sync(~0u, e1, srcB);
        float x2 = __shfl_sync(~0u, e2, srcA), x3 = __shfl_sync(~0u, e3, srcA);
        float y2 = __shfl_sync(~0u, e2, srcB), y3 = __shfl_sync(~0u, e3, srcB);
        A3[kk][0] = f2tf((q & 1) ? x1 : x0);
        A3[kk][1] = f2tf((q & 1) ? x3 : x2);
        A3[kk][2] = f2tf((q & 1) ? y1 : y0);
        A3[kk][3] = f2tf((q & 1) ? y3 : y2);
    }
    const float* gp = graph + ((long)b*N_ + n0 + w*16)*32;
    float* op = out + ((long)b*N_ + n0 + w*16)*32;
    #pragma unroll
    for (int of = 0; of < 4; of++) {
        int col = 2*q + 8*of;
        float bc0 = bc[col], bc1 = bc[col + 1];
        float2 gr0 = *(const float2*)(gp + g*32 + col);
        float2 gr1 = *(const float2*)(gp + (g + 8)*32 + col);
        float c[4] = { gr0.x + bc0, gr0.y + bc1, gr1.x + bc0, gr1.y + bc1 };
        const uint32_t* wb = &Wcs[(g + 8*of)*36 + q*8];
        uint4 f0 = *(const uint4*)wb;
        uint4 f1 = *(const uint4*)(wb + 4);
        mma_tf32(c, A3[0], f0.x, f0.y);
        mma_tf32(c, A3[1], f0.z, f0.w);
        mma_tf32(c, A3[2], f1.x, f1.y);
        mma_tf32(c, A3[3], f1.z, f1.w);
        *(float2*)(op + g*32 + col)       = make_float2(c[0], c[1]);
        *(float2*)(op + (g + 8)*32 + col) = make_float2(c[2], c[3]);
    }
}

// ===========================================================================
extern "C" void kernel_launch(void* const* d_in, const int* in_sizes, int n_in,
                              void* d_out, int out_size)
{
    const float* graph = (const float*)d_in[0];
    const float* img   = (const float*)d_in[1];
    const float* Wq    = (const float*)d_in[2];
    const float* bq    = (const float*)d_in[3];
    const float* Wk    = (const float*)d_in[4];
    const float* bk    = (const float*)d_in[5];
    const float* Wv    = (const float*)d_in[6];
    const float* bv    = (const float*)d_in[7];
    const float* Wc    = (const float*)d_in[8];
    const float* bc    = (const float*)d_in[9];
    float* out = (float*)d_out;

    k_proj_q   <<<B_*(N_/64), 256>>>(graph, Wq, bq);
    k_proj_kv  <<<B_*(L_/64), 256>>>(img, Wk, bk, Wv, bv);
    k_stats_mma<<<B_*(L_/128), 256>>>();
    k_final_mma<<<B_*(N_/128), 256>>>(graph, Wc, bc, out);
}

// round 4
// speedup vs baseline: 4.8200x; 1.3216x over previous
#include <cuda_runtime.h>
#include <cstdint>

#define B_  8
#define N_  4096
#define L_  4096
#define GC_ 32
#define IC_ 256

__device__ float    g_Q [B_*N_*GC_];    // [b][n][32], prescaled*QSCALE, tf32-rounded
__device__ float    g_KT[B_*L_*GC_];    // [b][l][32], tf32-rounded
__device__ float    g_VT[B_*L_*GC_];    // [b][l][32], raw f32
__device__ uint32_t g_Vb[B_*GC_*(L_/2)];// [b][c][l2] bf16x2 of V*Dinv (lo=even l)

#define QSCALE 0.2550668292560464f  // (1/sqrt(32)) * log2(e)

// ===========================================================================
// helpers
// ===========================================================================
__device__ __forceinline__ uint32_t f2tf(float f) {
    uint32_t u;
    asm("cvt.rna.tf32.f32 %0, %1;" : "=r"(u) : "f"(f));
    return u;
}
__device__ __forceinline__ float ex2f(float x) {
    float y;
    asm("ex2.approx.f32 %0, %1;" : "=f"(y) : "f"(x));
    return y;
}
__device__ __forceinline__ uint32_t pk_bf16x2(float hi, float lo) {
    uint32_t r;
    asm("cvt.rn.bf16x2.f32 %0, %1, %2;" : "=r"(r) : "f"(hi), "f"(lo));
    return r;
}
__device__ __forceinline__ void mma_tf32(float c[4], const uint32_t a[4],
                                         uint32_t b0, uint32_t b1) {
    asm volatile("mma.sync.aligned.m16n8k8.row.col.f32.tf32.tf32.f32 "
        "{%0,%1,%2,%3}, {%4,%5,%6,%7}, {%8,%9}, {%0,%1,%2,%3};"
        : "+f"(c[0]), "+f"(c[1]), "+f"(c[2]), "+f"(c[3])
        : "r"(a[0]), "r"(a[1]), "r"(a[2]), "r"(a[3]), "r"(b0), "r"(b1));
}
__device__ __forceinline__ void mma_bf16(float c[4], const uint32_t a[4],
                                         uint32_t b0, uint32_t b1) {
    asm volatile("mma.sync.aligned.m16n8k16.row.col.f32.bf16.bf16.f32 "
        "{%0,%1,%2,%3}, {%4,%5,%6,%7}, {%8,%9}, {%0,%1,%2,%3};"
        : "+f"(c[0]), "+f"(c[1]), "+f"(c[2]), "+f"(c[3])
        : "r"(a[0]), "r"(a[1]), "r"(a[2]), "r"(a[3]), "r"(b0), "r"(b1));
}

// ===========================================================================
// Kernel 1: Q projection, folds QSCALE, writes tf32-rounded
// ===========================================================================
__global__ __launch_bounds__(256) void k_proj_q(
    const float* __restrict__ graph, const float* __restrict__ Wq,
    const float* __restrict__ bq)
{
    __shared__ float WqS[GC_*33];
    __shared__ float gS[64*GC_];
    int b  = blockIdx.x >> 6;
    int n0 = (blockIdx.x & 63) * 64;
    int tid = threadIdx.x;

    for (int i = tid; i < GC_*GC_; i += 256)
        WqS[(i>>5)*33 + (i&31)] = Wq[i];
    const float* gp = graph + ((long)b*N_ + n0)*GC_;
    for (int i = tid; i < 64*GC_; i += 256) gS[i] = gp[i];
    __syncthreads();

    int o = tid & 31, nb = tid >> 5;
    float bias = bq[o];
    #pragma unroll
    for (int j = 0; j < 8; j++) {
        int n = nb + j*8;
        float acc = bias;
        #pragma unroll
        for (int c = 0; c < 32; c++) acc += WqS[o*33+c] * gS[n*32+c];
        ((uint32_t*)g_Q)[((long)b*N_ + n0 + n)*GC_ + o] = f2tf(acc * QSCALE);
    }
}

// ===========================================================================
// Kernel 2: K/V projection (K tf32-rounded, V raw)
// ===========================================================================
__global__ __launch_bounds__(256) void k_proj_kv(
    const float* __restrict__ img,
    const float* __restrict__ Wk, const float* __restrict__ bk,
    const float* __restrict__ Wv, const float* __restrict__ bv)
{
    __shared__ float imgS[32*64];
    __shared__ float WkS[32*33];
    __shared__ float WvS[32*33];
    int b  = blockIdx.x >> 6;
    int l0 = (blockIdx.x & 63) * 64;
    int tid = threadIdx.x;
    int lg = tid >> 4;
    int og = tid & 15;
    bool isK = og < 8;
    int obase = (og & 7) * 4;

    float acc[4][4];
    #pragma unroll
    for (int a = 0; a < 4; a++)
        #pragma unroll
        for (int c = 0; c < 4; c++) acc[a][c] = 0.f;

    for (int c0 = 0; c0 < IC_; c0 += 32) {
        __syncthreads();
        for (int i = tid; i < 32*64; i += 256) {
            int ci = i >> 6, li = i & 63;
            imgS[i] = img[((long)b*IC_ + c0 + ci)*L_ + l0 + li];
        }
        for (int i = tid; i < 32*32; i += 256) {
            int o = i >> 5, ci = i & 31;
            WkS[o*33+ci] = Wk[o*IC_ + c0 + ci];
            WvS[o*33+ci] = Wv[o*IC_ + c0 + ci];
        }
        __syncthreads();
        const float* Ws = isK ? WkS : WvS;
        #pragma unroll
        for (int ci = 0; ci < 32; ci++) {
            float4 iv = *(const float4*)&imgS[ci*64 + lg*4];
            #pragma unroll
            for (int jo = 0; jo < 4; jo++) {
                float w = Ws[(obase+jo)*33 + ci];
                acc[jo][0] += w*iv.x; acc[jo][1] += w*iv.y;
                acc[jo][2] += w*iv.z; acc[jo][3] += w*iv.w;
            }
        }
    }
    const float* bias = isK ? bk : bv;
    #pragma unroll
    for (int jo = 0; jo < 4; jo++) {
        float bs = bias[obase+jo];
        #pragma unroll
        for (int jl = 0; jl < 4; jl++) {
            long idx = ((long)b*L_ + l0 + lg*4 + jl)*GC_ + obase + jo;
            float v = acc[jo][jl] + bs;
            if (isK) ((uint32_t*)g_KT)[idx] = f2tf(v);
            else     g_VT[idx] = v;
        }
    }
}

// ===========================================================================
// Kernel 3: stats + V' production.
// S'[l,n] = K·Qᵀ (tf32 mma); D[l] = Σ_n exp2(s); then
// g_Vb[b][c][l2] = bf16x2( V[2l2+1][c]*Dinv , V[2l2][c]*Dinv ).
// Block: 8 warps × 32 l-rows = 256 l. grid = B*(L/256) = 128.
// Qs layout: [n][pos(k)], pos(k) = (k&3)*8 + (k>>2), pitch 36.
// ===========================================================================
__global__ __launch_bounds__(256, 1) void k_stats_mma()
{
    __shared__ __align__(16) uint32_t Qs[128*36];
    __shared__ float dinvS[256];
    int tid = threadIdx.x, w = tid >> 5, lane = tid & 31;
    int q = lane & 3, g = lane >> 2;
    int b = blockIdx.x >> 4, l0 = (blockIdx.x & 15) * 256;

    // A frags = K rows (pre-rounded tf32): 2 M-tiles of 16
    uint32_t A[2][4][4];
    #pragma unroll
    for (int mt = 0; mt < 2; mt++) {
        const uint32_t* kp = (const uint32_t*)g_KT +
            ((long)b*L_ + l0 + w*32 + mt*16)*32;
        #pragma unroll
        for (int kk = 0; kk < 4; kk++) {
            A[mt][kk][0] = kp[ g   *32 + 8*kk + q    ];
            A[mt][kk][1] = kp[(g+8)*32 + 8*kk + q    ];
            A[mt][kk][2] = kp[ g   *32 + 8*kk + q + 4];
            A[mt][kk][3] = kp[(g+8)*32 + 8*kk + q + 4];
        }
    }

    float d[2][2] = {{0.f,0.f},{0.f,0.f}};
    for (int nc = 0; nc < 32; nc++) {
        __syncthreads();
        const uint4* qp = (const uint4*)(g_Q + ((long)b*N_ + nc*128)*32);
        #pragma unroll
        for (int it = 0; it < 4; it++) {
            int i = tid + it*256;
            int r = i >> 3, t = i & 7;
            uint4 v = qp[i];
            Qs[r*36 +  0 + t] = v.x;
            Qs[r*36 +  8 + t] = v.y;
            Qs[r*36 + 16 + t] = v.z;
            Qs[r*36 + 24 + t] = v.w;
        }
        __syncthreads();
        #pragma unroll 4
        for (int j = 0; j < 16; j++) {
            const uint32_t* bp = &Qs[(g + 8*j)*36 + q*8];
            uint4 f0 = *(const uint4*)bp;
            uint4 f1 = *(const uint4*)(bp + 4);
            #pragma unroll
            for (int mt = 0; mt < 2; mt++) {
                float c[4] = {0.f, 0.f, 0.f, 0.f};
                mma_tf32(c, A[mt][0], f0.x, f0.y);
                mma_tf32(c, A[mt][1], f0.z, f0.w);
                mma_tf32(c, A[mt][2], f1.x, f1.y);
                mma_tf32(c, A[mt][3], f1.z, f1.w);
                d[mt][0] += ex2f(c[0]) + ex2f(c[1]);
                d[mt][1] += ex2f(c[2]) + ex2f(c[3]);
            }
        }
    }
    #pragma unroll
    for (int mt = 0; mt < 2; mt++) {
        #pragma unroll
        for (int h = 0; h < 2; h++) {
            float dv = d[mt][h];
            dv += __shfl_xor_sync(~0u, dv, 1);
            dv += __shfl_xor_sync(~0u, dv, 2);
            if (q == 0) dinvS[w*32 + mt*16 + h*8 + g] = 1.0f / dv;
        }
    }
    __syncthreads();

    // V' production: stage 128 l-rows at a time through smem
    float* Vst = (float*)Qs;   // 128*33 <= 128*36
    for (int h = 0; h < 2; h++) {
        __syncthreads();
        const float* vp = g_VT + ((long)b*L_ + l0 + h*128)*32;
        #pragma unroll
        for (int it = 0; it < 16; it++) {
            int i = tid + it*256;
            Vst[(i >> 5)*33 + (i & 31)] = vp[i];
        }
        __syncthreads();
        uint32_t* dst = g_Vb + ((long)b*GC_)*(L_/2) + (l0 >> 1) + h*64;
        #pragma unroll
        for (int it = 0; it < 8; it++) {
            int i = tid + it*256;
            int c = i >> 6, l2 = i & 63;
            float lo = Vst[(2*l2    )*33 + c] * dinvS[h*128 + 2*l2    ];
            float hi = Vst[(2*l2 + 1)*33 + c] * dinvS[h*128 + 2*l2 + 1];
            dst[(long)c*(L_/2) + l2] = pk_bf16x2(hi, lo);
        }
    }
}

// ===========================================================================
// Kernel 4: final.
//   GEMM1 S[n,l]=Q·Kᵀ (tf32) -> ex2 -> bf16 pack (C-frag == A-frag!)
//   GEMM2 msg += P·V' (bf16 m16n8k16), epilogue GEMM3 out = graph+bc+msg·Wcᵀ.
// Block: 8 warps × 32 n-rows = 256 n. grid = B*(N/256) = 128.
// Ks:  [l][pos(k)] pitch 36 (tf32 words)
// Vbs: [c][l2] pitch 68 (bf16x2 words, conflict-free B-frag loads)
// Wb:  [o][c2] pitch 17 (bf16x2)
// ===========================================================================
__global__ __launch_bounds__(256, 1) void k_final_mma(
    const float* __restrict__ graph, const float* __restrict__ Wc,
    const float* __restrict__ bc, float* __restrict__ out)
{
    __shared__ __align__(16) uint32_t Ks[128*36];
    __shared__ uint32_t Vbs[32*68];
    __shared__ uint32_t Wb[32*17];
    int tid = threadIdx.x, w = tid >> 5, lane = tid & 31;
    int q = lane & 3, g = lane >> 2;
    int b = blockIdx.x >> 4, n0 = (blockIdx.x & 15) * 256;

    // A frags = Q rows (pre-rounded, prescaled): 2 M-tiles
    uint32_t A[2][4][4];
    #pragma unroll
    for (int mt = 0; mt < 2; mt++) {
        const uint32_t* qp = (const uint32_t*)g_Q +
            ((long)b*N_ + n0 + w*32 + mt*16)*32;
        #pragma unroll
        for (int kk = 0; kk < 4; kk++) {
            A[mt][kk][0] = qp[ g   *32 + 8*kk + q    ];
            A[mt][kk][1] = qp[(g+8)*32 + 8*kk + q    ];
            A[mt][kk][2] = qp[ g   *32 + 8*kk + q + 4];
            A[mt][kk][3] = qp[(g+8)*32 + 8*kk + q + 4];
        }
    }
    // Wc -> bf16x2 [o][c2]
    for (int i = tid; i < 32*16; i += 256) {
        int o = i >> 4, c2 = i & 15;
        Wb[o*17 + c2] = pk_bf16x2(Wc[o*32 + 2*c2 + 1], Wc[o*32 + 2*c2]);
    }

    float mc[2][4][4];
    #pragma unroll
    for (int mt = 0; mt < 2; mt++)
        #pragma unroll
        for (int cf = 0; cf < 4; cf++)
            #pragma unroll
            for (int x = 0; x < 4; x++) mc[mt][cf][x] = 0.f;

    const uint32_t* vbsrc = g_Vb + ((long)b*GC_)*(L_/2);

    for (int lc = 0; lc < 32; lc++) {
        __syncthreads();
        const uint4* kp = (const uint4*)(g_KT + ((long)b*L_ + lc*128)*32);
        #pragma unroll
        for (int it = 0; it < 4; it++) {
            int i = tid + it*256;
            int r = i >> 3, t = i & 7;
            uint4 v = kp[i];
            Ks[r*36 +  0 + t] = v.x;
            Ks[r*36 +  8 + t] = v.y;
            Ks[r*36 + 16 + t] = v.z;
            Ks[r*36 + 24 + t] = v.w;
        }
        #pragma unroll
        for (int it = 0; it < 8; it++) {
            int i = tid + it*256;
            int c = i >> 6, l2 = i & 63;
            Vbs[c*68 + l2] = vbsrc[(long)c*(L_/2) + lc*64 + l2];
        }
        __syncthreads();

        #pragma unroll 2
        for (int s = 0; s < 8; s++) {
            // GEMM1 B-frags for j = 2s, 2s+1
            const uint32_t* bpa = &Ks[(g + 16*s    )*36 + q*8];
            const uint32_t* bpb = &Ks[(g + 16*s + 8)*36 + q*8];
            uint4 f0a = *(const uint4*)bpa, f1a = *(const uint4*)(bpa + 4);
            uint4 f0b = *(const uint4*)bpb, f1b = *(const uint4*)(bpb + 4);
            // GEMM2 B-frags (shared across mt)
            uint32_t vb0[4], vb1[4];
            #pragma unroll
            for (int cf = 0; cf < 4; cf++) {
                vb0[cf] = Vbs[(g + 8*cf)*68 + 8*s + q    ];
                vb1[cf] = Vbs[(g + 8*cf)*68 + 8*s + q + 4];
            }
            #pragma unroll
            for (int mt = 0; mt < 2; mt++) {
                float c0[4] = {0.f,0.f,0.f,0.f};
                float c1[4] = {0.f,0.f,0.f,0.f};
                mma_tf32(c0, A[mt][0], f0a.x, f0a.y);
                mma_tf32(c0, A[mt][1], f0a.z, f0a.w);
                mma_tf32(c0, A[mt][2], f1a.x, f1a.y);
                mma_tf32(c0, A[mt][3], f1a.z, f1a.w);
                mma_tf32(c1, A[mt][0], f0b.x, f0b.y);
                mma_tf32(c1, A[mt][1], f0b.z, f0b.w);
                mma_tf32(c1, A[mt][2], f1b.x, f1b.y);
                mma_tf32(c1, A[mt][3], f1b.z, f1b.w);
                uint32_t A2[4];
                A2[0] = pk_bf16x2(ex2f(c0[1]), ex2f(c0[0]));
                A2[1] = pk_bf16x2(ex2f(c0[3]), ex2f(c0[2]));
                A2[2] = pk_bf16x2(ex2f(c1[1]), ex2f(c1[0]));
                A2[3] = pk_bf16x2(ex2f(c1[3]), ex2f(c1[2]));
                #pragma unroll
                for (int cf = 0; cf < 4; cf++)
                    mma_bf16(mc[mt][cf], A2, vb0[cf], vb1[cf]);
            }
        }
    }

    // Epilogue GEMM3: out = graph + bc + msg·Wcᵀ  (bf16 mma)
    #pragma unroll
    for (int mt = 0; mt < 2; mt++) {
        uint32_t A3[2][4];
        #pragma unroll
        for (int t = 0; t < 2; t++) {
            A3[t][0] = pk_bf16x2(mc[mt][2*t  ][1], mc[mt][2*t  ][0]);
            A3[t][1] = pk_bf16x2(mc[mt][2*t  ][3], mc[mt][2*t  ][2]);
            A3[t][2] = pk_bf16x2(mc[mt][2*t+1][1], mc[mt][2*t+1][0]);
            A3[t][3] = pk_bf16x2(mc[mt][2*t+1][3], mc[mt][2*t+1][2]);
        }
        long nbase = (long)b*N_ + n0 + w*32 + mt*16;
        const float* gp = graph + nbase*32;
        float* op = out + nbase*32;
        #pragma unroll
        for (int of = 0; of < 4; of++) {
            int col = 8*of + 2*q;
            float bc0 = bc[col], bc1 = bc[col + 1];
            float2 gr0 = *(const float2*)(gp + g*32 + col);
            float2 gr1 = *(const float2*)(gp + (g + 8)*32 + col);
            float c[4] = { gr0.x + bc0, gr0.y + bc1, gr1.x + bc0, gr1.y + bc1 };
            #pragma unroll
            for (int t = 0; t < 2; t++) {
                uint32_t b0 = Wb[(g + 8*of)*17 + 8*t + q    ];
                uint32_t b1 = Wb[(g + 8*of)*17 + 8*t + q + 4];
                mma_bf16(c, A3[t], b0, b1);
            }
            *(float2*)(op + g*32 + col)       = make_float2(c[0], c[1]);
            *(float2*)(op + (g + 8)*32 + col) = make_float2(c[2], c[3]);
        }
    }
}

// ===========================================================================
extern "C" void kernel_launch(void* const* d_in, const int* in_sizes, int n_in,
                              void* d_out, int out_size)
{
    const float* graph = (const float*)d_in[0];
    const float* img   = (const float*)d_in[1];
    const float* Wq    = (const float*)d_in[2];
    const float* bq    = (const float*)d_in[3];
    const float* Wk    = (const float*)d_in[4];
    const float* bk    = (const float*)d_in[5];
    const float* Wv    = (const float*)d_in[6];
    const float* bv    = (const float*)d_in[7];
    const float* Wc    = (const float*)d_in[8];
    const float* bc    = (const float*)d_in[9];
    float* out = (float*)d_out;

    k_proj_q   <<<B_*(N_/64), 256>>>(graph, Wq, bq);
    k_proj_kv  <<<B_*(L_/64), 256>>>(img, Wk, bk, Wv, bv);
    k_stats_mma<<<B_*(L_/256), 256>>>();
    k_final_mma<<<B_*(N_/256), 256>>>(graph, Wc, bc, out);
}

// round 5
// speedup vs baseline: 6.6452x; 1.3787x over previous
#include <cuda_runtime.h>
#include <cstdint>

#define B_  8
#define N_  4096
#define L_  4096
#define GC_ 32
#define IC_ 256

__device__ uint32_t g_Qb[B_*N_*16];      // [b][n][k2] bf16x2 (Q*QSCALE)
__device__ uint32_t g_Kb[B_*L_*16];      // [b][l][k2] bf16x2
__device__ float    g_VT[B_*L_*GC_];     // [b][l][c] raw f32
__device__ uint32_t g_Vb[B_*GC_*(L_/2)]; // [b][c][l2] bf16x2 of V*Dinv

#define QSCALE 0.2550668292560464f  // (1/sqrt(32)) * log2(e)

// ===========================================================================
// helpers
// ===========================================================================
__device__ __forceinline__ uint32_t smem_u32(const void* p) {
    uint32_t a;
    asm("{ .reg .u64 t; cvta.to.shared.u64 t, %1; cvt.u32.u64 %0, t; }"
        : "=r"(a) : "l"(p));
    return a;
}
__device__ __forceinline__ float ex2f(float x) {
    float y;
    asm("ex2.approx.f32 %0, %1;" : "=f"(y) : "f"(x));
    return y;
}
__device__ __forceinline__ uint32_t pk_bf16x2(float hi, float lo) {
    uint32_t r;
    asm("cvt.rn.bf16x2.f32 %0, %1, %2;" : "=r"(r) : "f"(hi), "f"(lo));
    return r;
}
__device__ __forceinline__ void mma_bf16(float c[4], const uint32_t a[4],
                                         uint32_t b0, uint32_t b1) {
    asm volatile("mma.sync.aligned.m16n8k16.row.col.f32.bf16.bf16.f32 "
        "{%0,%1,%2,%3}, {%4,%5,%6,%7}, {%8,%9}, {%0,%1,%2,%3};"
        : "+f"(c[0]), "+f"(c[1]), "+f"(c[2]), "+f"(c[3])
        : "r"(a[0]), "r"(a[1]), "r"(a[2]), "r"(a[3]), "r"(b0), "r"(b1));
}
__device__ __forceinline__ void cp16(uint32_t s, const void* g) {
    asm volatile("cp.async.ca.shared.global [%0], [%1], 16;"
                 :: "r"(s), "l"(g) : "memory");
}
#define CP_COMMIT() asm volatile("cp.async.commit_group;" ::: "memory")
#define CP_WAIT1()  asm volatile("cp.async.wait_group 1;" ::: "memory")
#define CP_WAIT0()  asm volatile("cp.async.wait_group 0;" ::: "memory")

// ===========================================================================
// Kernel 1: Q projection -> packed bf16x2, QSCALE folded
// ===========================================================================
__global__ __launch_bounds__(256) void k_proj_q(
    const float* __restrict__ graph, const float* __restrict__ Wq,
    const float* __restrict__ bq)
{
    __shared__ float WqS[GC_*33];
    __shared__ float gS[64*GC_];
    int b  = blockIdx.x >> 6;
    int n0 = (blockIdx.x & 63) * 64;
    int tid = threadIdx.x;

    for (int i = tid; i < GC_*GC_; i += 256)
        WqS[(i>>5)*33 + (i&31)] = Wq[i];
    const float* gp = graph + ((long)b*N_ + n0)*GC_;
    for (int i = tid; i < 64*GC_; i += 256) gS[i] = gp[i];
    __syncthreads();

    int o2 = tid & 15, nb = tid >> 4;
    float b0 = bq[2*o2], b1 = bq[2*o2 + 1];
    #pragma unroll
    for (int j = 0; j < 4; j++) {
        int n = nb + 16*j;
        float a0 = b0, a1 = b1;
        #pragma unroll
        for (int c = 0; c < 32; c++) {
            float gv = gS[n*32 + c];
            a0 += WqS[(2*o2    )*33 + c] * gv;
            a1 += WqS[(2*o2 + 1)*33 + c] * gv;
        }
        g_Qb[((long)b*N_ + n0 + n)*16 + o2] = pk_bf16x2(a1*QSCALE, a0*QSCALE);
    }
}

// ===========================================================================
// Kernel 2: K/V projection (K packed bf16x2, V raw f32)
// ===========================================================================
__global__ __launch_bounds__(256) void k_proj_kv(
    const float* __restrict__ img,
    const float* __restrict__ Wk, const float* __restrict__ bk,
    const float* __restrict__ Wv, const float* __restrict__ bv)
{
    __shared__ float imgS[32*64];
    __shared__ float WkS[32*33];
    __shared__ float WvS[32*33];
    int b  = blockIdx.x >> 6;
    int l0 = (blockIdx.x & 63) * 64;
    int tid = threadIdx.x;
    int lg = tid >> 4;
    int og = tid & 15;
    bool isK = og < 8;
    int obase = (og & 7) * 4;

    float acc[4][4];
    #pragma unroll
    for (int a = 0; a < 4; a++)
        #pragma unroll
        for (int c = 0; c < 4; c++) acc[a][c] = 0.f;

    for (int c0 = 0; c0 < IC_; c0 += 32) {
        __syncthreads();
        for (int i = tid; i < 32*64; i += 256) {
            int ci = i >> 6, li = i & 63;
            imgS[i] = img[((long)b*IC_ + c0 + ci)*L_ + l0 + li];
        }
        for (int i = tid; i < 32*32; i += 256) {
            int o = i >> 5, ci = i & 31;
            WkS[o*33+ci] = Wk[o*IC_ + c0 + ci];
            WvS[o*33+ci] = Wv[o*IC_ + c0 + ci];
        }
        __syncthreads();
        const float* Ws = isK ? WkS : WvS;
        #pragma unroll
        for (int ci = 0; ci < 32; ci++) {
            float4 iv = *(const float4*)&imgS[ci*64 + lg*4];
            #pragma unroll
            for (int jo = 0; jo < 4; jo++) {
                float w = Ws[(obase+jo)*33 + ci];
                acc[jo][0] += w*iv.x; acc[jo][1] += w*iv.y;
                acc[jo][2] += w*iv.z; acc[jo][3] += w*iv.w;
            }
        }
    }
    if (isK) {
        float bs0 = bk[obase], bs1 = bk[obase+1], bs2 = bk[obase+2], bs3 = bk[obase+3];
        #pragma unroll
        for (int jl = 0; jl < 4; jl++) {
            long l = (long)b*L_ + l0 + lg*4 + jl;
            g_Kb[l*16 + obase/2    ] = pk_bf16x2(acc[1][jl]+bs1, acc[0][jl]+bs0);
            g_Kb[l*16 + obase/2 + 1] = pk_bf16x2(acc[3][jl]+bs3, acc[2][jl]+bs2);
        }
    } else {
        #pragma unroll
        for (int jo = 0; jo < 4; jo++) {
            float bs = bv[obase+jo];
            #pragma unroll
            for (int jl = 0; jl < 4; jl++)
                g_VT[((long)b*L_ + l0 + lg*4 + jl)*GC_ + obase + jo] = acc[jo][jl] + bs;
        }
    }
}

// ===========================================================================
// Kernel 3: stats + V' production (bf16 GEMM1, cp.async double buffer).
// Warp owns 32 l-rows (2 M-tiles); D[l] = Σ_n exp2(s). Then V' = V·Dinv
// packed bf16x2 into g_Vb.
// Qs: [buf][n][k2] pitch 20 (conflict-free B-frags).
// ===========================================================================
#define QP 20

__global__ __launch_bounds__(256, 1) void k_stats_mma()
{
    __shared__ __align__(16) uint32_t Qs[2][128*QP];
    __shared__ float dinvS[256];
    int tid = threadIdx.x, w = tid >> 5, lane = tid & 31;
    int q = lane & 3, g = lane >> 2;
    int b = blockIdx.x >> 4, l0 = (blockIdx.x & 15) * 256;
    uint32_t qs_b = smem_u32(Qs);

    // A frags = K rows (packed bf16x2)
    uint32_t A[2][2][4];
    #pragma unroll
    for (int mt = 0; mt < 2; mt++) {
        const uint32_t* kp = g_Kb + ((long)b*L_ + l0 + w*32 + mt*16)*16;
        #pragma unroll
        for (int kk = 0; kk < 2; kk++) {
            A[mt][kk][0] = kp[ g   *16 + 8*kk + q    ];
            A[mt][kk][1] = kp[(g+8)*16 + 8*kk + q    ];
            A[mt][kk][2] = kp[ g   *16 + 8*kk + q + 4];
            A[mt][kk][3] = kp[(g+8)*16 + 8*kk + q + 4];
        }
    }

    auto prefetch = [&](int nc, int buf) {
        const uint32_t* src = g_Qb + ((long)b*N_ + nc*128)*16;
        #pragma unroll
        for (int it = 0; it < 2; it++) {
            int i = tid + it*256;
            int r = i >> 2, t = i & 3;
            cp16(qs_b + (buf*128*QP + r*QP + 4*t)*4, src + r*16 + 4*t);
        }
        CP_COMMIT();
    };
    prefetch(0, 0);

    float d[2][2] = {{0.f,0.f},{0.f,0.f}};
    for (int nc = 0; nc < 32; nc++) {
        if (nc < 31) { prefetch(nc + 1, (nc + 1) & 1); CP_WAIT1(); }
        else CP_WAIT0();
        __syncthreads();
        const uint32_t* Q = &Qs[nc & 1][0];
        #pragma unroll 4
        for (int j = 0; j < 16; j++) {
            const uint32_t* bp = &Q[(g + 8*j)*QP + q];
            uint32_t b00 = bp[0], b01 = bp[4];
            uint32_t b10 = bp[8], b11 = bp[12];
            #pragma unroll
            for (int mt = 0; mt < 2; mt++) {
                float c[4] = {0.f, 0.f, 0.f, 0.f};
                mma_bf16(c, A[mt][0], b00, b01);
                mma_bf16(c, A[mt][1], b10, b11);
                d[mt][0] += ex2f(c[0]) + ex2f(c[1]);
                d[mt][1] += ex2f(c[2]) + ex2f(c[3]);
            }
        }
        __syncthreads();
    }
    #pragma unroll
    for (int mt = 0; mt < 2; mt++) {
        #pragma unroll
        for (int h = 0; h < 2; h++) {
            float dv = d[mt][h];
            dv += __shfl_xor_sync(~0u, dv, 1);
            dv += __shfl_xor_sync(~0u, dv, 2);
            if (q == 0) dinvS[w*32 + mt*16 + h*8 + g] = 1.0f / dv;
        }
    }
    __syncthreads();

    // V' production, staged through Qs (reused as float scratch)
    float* Vst = (float*)&Qs[0][0];   // needs 128*33=4224 <= 5120
    for (int h = 0; h < 2; h++) {
        __syncthreads();
        const float* vp = g_VT + ((long)b*L_ + l0 + h*128)*32;
        #pragma unroll
        for (int it = 0; it < 16; it++) {
            int i = tid + it*256;
            Vst[(i >> 5)*33 + (i & 31)] = vp[i];
        }
        __syncthreads();
        uint32_t* dst = g_Vb + ((long)b*GC_)*(L_/2) + (l0 >> 1) + h*64;
        #pragma unroll
        for (int it = 0; it < 8; it++) {
            int i = tid + it*256;
            int c = i >> 6, l2 = i & 63;
            float lo = Vst[(2*l2    )*33 + c] * dinvS[h*128 + 2*l2    ];
            float hi = Vst[(2*l2 + 1)*33 + c] * dinvS[h*128 + 2*l2 + 1];
            dst[(long)c*(L_/2) + l2] = pk_bf16x2(hi, lo);
        }
    }
}

// ===========================================================================
// Kernel 4: final (all-bf16 MMA, cp.async double buffer).
//   GEMM1 S[n,l]=Q·Kᵀ -> ex2 -> pack -> GEMM2 msg += P·V'
//   epilogue GEMM3 out = graph + bc + msg·Wcᵀ.
// Ks:  [buf][l][k2] pitch 20;  Vbs: [buf][c][l2] pitch 68;  Wb: [o][c2] pitch 17.
// ===========================================================================
#define KP 20
#define VP 68

__global__ __launch_bounds__(256, 1) void k_final_mma(
    const float* __restrict__ graph, const float* __restrict__ Wc,
    const float* __restrict__ bc, float* __restrict__ out)
{
    __shared__ __align__(16) uint32_t Ks[2][128*KP];
    __shared__ __align__(16) uint32_t Vbs[2][32*VP];
    __shared__ uint32_t Wb[32*17];
    int tid = threadIdx.x, w = tid >> 5, lane = tid & 31;
    int q = lane & 3, g = lane >> 2;
    int b = blockIdx.x >> 4, n0 = (blockIdx.x & 15) * 256;
    uint32_t ks_b = smem_u32(Ks), vb_b = smem_u32(Vbs);

    // A frags = Q rows (packed, prescaled)
    uint32_t A[2][2][4];
    #pragma unroll
    for (int mt = 0; mt < 2; mt++) {
        const uint32_t* qp = g_Qb + ((long)b*N_ + n0 + w*32 + mt*16)*16;
        #pragma unroll
        for (int kk = 0; kk < 2; kk++) {
            A[mt][kk][0] = qp[ g   *16 + 8*kk + q    ];
            A[mt][kk][1] = qp[(g+8)*16 + 8*kk + q    ];
            A[mt][kk][2] = qp[ g   *16 + 8*kk + q + 4];
            A[mt][kk][3] = qp[(g+8)*16 + 8*kk + q + 4];
        }
    }
    for (int i = tid; i < 32*16; i += 256) {
        int o = i >> 4, c2 = i & 15;
        Wb[o*17 + c2] = pk_bf16x2(Wc[o*32 + 2*c2 + 1], Wc[o*32 + 2*c2]);
    }

    const uint32_t* vbsrc = g_Vb + ((long)b*GC_)*(L_/2);
    auto prefetch = [&](int lc, int buf) {
        const uint32_t* ksrc = g_Kb + ((long)b*L_ + lc*128)*16;
        #pragma unroll
        for (int it = 0; it < 2; it++) {
            int i = tid + it*256;
            int r = i >> 2, t = i & 3;
            cp16(ks_b + (buf*128*KP + r*KP + 4*t)*4, ksrc + r*16 + 4*t);
        }
        #pragma unroll
        for (int it = 0; it < 2; it++) {
            int i = tid + it*256;
            int c = i >> 4, t2 = i & 15;
            cp16(vb_b + (buf*32*VP + c*VP + 4*t2)*4,
                 vbsrc + (long)c*(L_/2) + lc*64 + 4*t2);
        }
        CP_COMMIT();
    };
    prefetch(0, 0);

    float mc[2][4][4];
    #pragma unroll
    for (int mt = 0; mt < 2; mt++)
        #pragma unroll
        for (int cf = 0; cf < 4; cf++)
            #pragma unroll
            for (int x = 0; x < 4; x++) mc[mt][cf][x] = 0.f;

    for (int lc = 0; lc < 32; lc++) {
        if (lc < 31) { prefetch(lc + 1, (lc + 1) & 1); CP_WAIT1(); }
        else CP_WAIT0();
        __syncthreads();
        const uint32_t* K = &Ks[lc & 1][0];
        const uint32_t* V = &Vbs[lc & 1][0];

        #pragma unroll 2
        for (int s = 0; s < 8; s++) {
            const uint32_t* bpa = &K[(g + 16*s    )*KP + q];
            const uint32_t* bpb = &K[(g + 16*s + 8)*KP + q];
            uint32_t ba00 = bpa[0], ba01 = bpa[4], ba10 = bpa[8], ba11 = bpa[12];
            uint32_t bb00 = bpb[0], bb01 = bpb[4], bb10 = bpb[8], bb11 = bpb[12];
            uint32_t vb0[4], vb1[4];
            #pragma unroll
            for (int cf = 0; cf < 4; cf++) {
                vb0[cf] = V[(g + 8*cf)*VP + 8*s + q    ];
                vb1[cf] = V[(g + 8*cf)*VP + 8*s + q + 4];
            }
            #pragma unroll
            for (int mt = 0; mt < 2; mt++) {
                float c0[4] = {0.f,0.f,0.f,0.f};
                float c1[4] = {0.f,0.f,0.f,0.f};
                mma_bf16(c0, A[mt][0], ba00, ba01);
                mma_bf16(c0, A[mt][1], ba10, ba11);
                mma_bf16(c1, A[mt][0], bb00, bb01);
                mma_bf16(c1, A[mt][1], bb10, bb11);
                uint32_t A2[4];
                A2[0] = pk_bf16x2(ex2f(c0[1]), ex2f(c0[0]));
                A2[1] = pk_bf16x2(ex2f(c0[3]), ex2f(c0[2]));
                A2[2] = pk_bf16x2(ex2f(c1[1]), ex2f(c1[0]));
                A2[3] = pk_bf16x2(ex2f(c1[3]), ex2f(c1[2]));
                #pragma unroll
                for (int cf = 0; cf < 4; cf++)
                    mma_bf16(mc[mt][cf], A2, vb0[cf], vb1[cf]);
            }
        }
        __syncthreads();
    }

    // Epilogue GEMM3: out = graph + bc + msg·Wcᵀ
    #pragma unroll
    for (int mt = 0; mt < 2; mt++) {
        uint32_t A3[2][4];
        #pragma unroll
        for (int t = 0; t < 2; t++) {
            A3[t][0] = pk_bf16x2(mc[mt][2*t  ][1], mc[mt][2*t  ][0]);
            A3[t][1] = pk_bf16x2(mc[mt][2*t  ][3], mc[mt][2*t  ][2]);
            A3[t][2] = pk_bf16x2(mc[mt][2*t+1][1], mc[mt][2*t+1][0]);
            A3[t][3] = pk_bf16x2(mc[mt][2*t+1][3], mc[mt][2*t+1][2]);
        }
        long nbase = (long)b*N_ + n0 + w*32 + mt*16;
        const float* gp = graph + nbase*32;
        float* op = out + nbase*32;
        #pragma unroll
        for (int of = 0; of < 4; of++) {
            int col = 8*of + 2*q;
            float bc0 = bc[col], bc1 = bc[col + 1];
            float2 gr0 = *(const float2*)(gp + g*32 + col);
            float2 gr1 = *(const float2*)(gp + (g + 8)*32 + col);
            float c[4] = { gr0.x + bc0, gr0.y + bc1, gr1.x + bc0, gr1.y + bc1 };
            #pragma unroll
            for (int t = 0; t < 2; t++) {
                uint32_t b0 = Wb[(g + 8*of)*17 + 8*t + q    ];
                uint32_t b1 = Wb[(g + 8*of)*17 + 8*t + q + 4];
                mma_bf16(c, A3[t], b0, b1);
            }
            *(float2*)(op + g*32 + col)       = make_float2(c[0], c[1]);
            *(float2*)(op + (g + 8)*32 + col) = make_float2(c[2], c[3]);
        }
    }
}

// ===========================================================================
extern "C" void kernel_launch(void* const* d_in, const int* in_sizes, int n_in,
                              void* d_out, int out_size)
{
    const float* graph = (const float*)d_in[0];
    const float* img   = (const float*)d_in[1];
    const float* Wq    = (const float*)d_in[2];
    const float* bq    = (const float*)d_in[3];
    const float* Wk    = (const float*)d_in[4];
    const float* bk    = (const float*)d_in[5];
    const float* Wv    = (const float*)d_in[6];
    const float* bv    = (const float*)d_in[7];
    const float* Wc    = (const float*)d_in[8];
    const float* bc    = (const float*)d_in[9];
    float* out = (float*)d_out;

    k_proj_q   <<<B_*(N_/64), 256>>>(graph, Wq, bq);
    k_proj_kv  <<<B_*(L_/64), 256>>>(img, Wk, bk, Wv, bv);
    k_stats_mma<<<B_*(L_/256), 256>>>();
    k_final_mma<<<B_*(N_/256), 256>>>(graph, Wc, bc, out);
}

// round 6
// speedup vs baseline: 6.8562x; 1.0318x over previous
#include <cuda_runtime.h>
#include <cstdint>

#define B_  8
#define N_  4096
#define L_  4096
#define GC_ 32
#define IC_ 256

__device__ uint32_t g_Qb [B_*N_*16];      // [b][n][k2] bf16x2 (Q*QSCALE)
__device__ uint32_t g_Kb [B_*L_*16];      // [b][l][k2] bf16x2
__device__ float    g_VTc[B_*GC_*L_];     // [b][c][l] raw f32 (channel-major)
__device__ uint32_t g_Vb [B_*GC_*(L_/2)]; // [b][c][l2] bf16x2 of V*Dinv

#define QSCALE 0.2550668292560464f  // (1/sqrt(32)) * log2(e)

// ===========================================================================
// helpers
// ===========================================================================
__device__ __forceinline__ uint32_t smem_u32(const void* p) {
    uint32_t a;
    asm("{ .reg .u64 t; cvta.to.shared.u64 t, %1; cvt.u32.u64 %0, t; }"
        : "=r"(a) : "l"(p));
    return a;
}
__device__ __forceinline__ float ex2f(float x) {
    float y;
    asm("ex2.approx.f32 %0, %1;" : "=f"(y) : "f"(x));
    return y;
}
// FMA/ALU-pipe exp2: rint range reduction + cubic minimax on [-0.5, 0.5]
// (rel err ~1.1e-4, below the bf16 pack noise downstream)
__device__ __forceinline__ float ex2p(float x) {
    x = fmaxf(x, -120.0f);
    int   i = __float2int_rn(x);
    float f = x - (float)i;
    float p = fmaf(f, 0.0559206f, 0.2426315f);
    p = fmaf(f, p, 0.69312096f);
    p = fmaf(f, p, 0.99992486f);
    return __int_as_float(__float_as_int(p) + (i << 23));
}
__device__ __forceinline__ uint32_t pk_bf16x2(float hi, float lo) {
    uint32_t r;
    asm("cvt.rn.bf16x2.f32 %0, %1, %2;" : "=r"(r) : "f"(hi), "f"(lo));
    return r;
}
__device__ __forceinline__ void mma_bf16(float c[4], const uint32_t a[4],
                                         uint32_t b0, uint32_t b1) {
    asm volatile("mma.sync.aligned.m16n8k16.row.col.f32.bf16.bf16.f32 "
        "{%0,%1,%2,%3}, {%4,%5,%6,%7}, {%8,%9}, {%0,%1,%2,%3};"
        : "+f"(c[0]), "+f"(c[1]), "+f"(c[2]), "+f"(c[3])
        : "r"(a[0]), "r"(a[1]), "r"(a[2]), "r"(a[3]), "r"(b0), "r"(b1));
}
__device__ __forceinline__ void cp16(uint32_t s, const void* g) {
    asm volatile("cp.async.ca.shared.global [%0], [%1], 16;"
                 :: "r"(s), "l"(g) : "memory");
}
#define CP_COMMIT() asm volatile("cp.async.commit_group;" ::: "memory")
#define CP_WAIT1()  asm volatile("cp.async.wait_group 1;" ::: "memory")
#define CP_WAIT0()  asm volatile("cp.async.wait_group 0;" ::: "memory")

// ===========================================================================
// Kernel 1: Q projection (SIMT, tiny) -> packed bf16x2, QSCALE folded
// ===========================================================================
__global__ __launch_bounds__(256) void k_proj_q(
    const float* __restrict__ graph, const float* __restrict__ Wq,
    const float* __restrict__ bq)
{
    __shared__ float WqS[GC_*33];
    __shared__ float gS[64*GC_];
    int b  = blockIdx.x >> 6;
    int n0 = (blockIdx.x & 63) * 64;
    int tid = threadIdx.x;

    for (int i = tid; i < GC_*GC_; i += 256)
        WqS[(i>>5)*33 + (i&31)] = Wq[i];
    const float* gp = graph + ((long)b*N_ + n0)*GC_;
    for (int i = tid; i < 64*GC_; i += 256) gS[i] = gp[i];
    __syncthreads();

    int o2 = tid & 15, nb = tid >> 4;
    float b0 = bq[2*o2], b1 = bq[2*o2 + 1];
    #pragma unroll
    for (int j = 0; j < 4; j++) {
        int n = nb + 16*j;
        float a0 = b0, a1 = b1;
        #pragma unroll
        for (int c = 0; c < 32; c++) {
            float gv = gS[n*32 + c];
            a0 += WqS[(2*o2    )*33 + c] * gv;
            a1 += WqS[(2*o2 + 1)*33 + c] * gv;
        }
        g_Qb[((long)b*N_ + n0 + n)*16 + o2] = pk_bf16x2(a1*QSCALE, a0*QSCALE);
    }
}

// ===========================================================================
// Kernel 2: K/V projection via bf16 MMA.
// A = [Wk;Wv] (64x256), B = img tile (256 l per CTA), C[64 o][256 l].
// K: shfl-transpose -> g_Kb[l][o2] bf16x2.  V: direct -> g_VTc[c][l] f32.
// grid = B*16 = 128, 256 threads. Dynamic smem ~163 KB.
// ===========================================================================
#define PW 132   // W smem pitch (words)
#define PI 260   // img smem pitch (f32 words)

__global__ __launch_bounds__(256, 1) void k_proj_kv_mma(
    const float* __restrict__ img,
    const float* __restrict__ Wk, const float* __restrict__ bk,
    const float* __restrict__ Wv, const float* __restrict__ bv)
{
    extern __shared__ uint32_t shm[];
    uint32_t* Wsm  = shm;                       // [64][PW]
    float*    img0 = (float*)(shm + 64*PW);     // [64][PI] x2 buffers
    float*    img1 = img0 + 64*PI;

    int tid = threadIdx.x, w = tid >> 5, lane = tid & 31;
    int q = lane & 3, g = lane >> 2;
    int b = blockIdx.x >> 4, l0 = (blockIdx.x & 15) * 256;

    // W smem fill: bf16x2 pairs over c
    #pragma unroll
    for (int t = 0; t < 32; t++) {
        int u = tid + t*256;
        int o = u >> 7, c2 = u & 127;
        const float* src = (o < 32) ? (Wk + o*IC_ + 2*c2) : (Wv + (o-32)*IC_ + 2*c2);
        float2 v = *(const float2*)src;
        Wsm[o*PW + c2] = pk_bf16x2(v.y, v.x);
    }

    auto pref = [&](int ks, float* dstbuf) {
        const float* src = img + ((long)b*IC_ + ks*64)*L_ + l0;
        uint32_t dstb = smem_u32(dstbuf);
        #pragma unroll
        for (int t = 0; t < 16; t++) {
            int u = tid + t*256;
            int c = u >> 6, col = (u & 63) * 4;
            cp16(dstb + (c*PI + col)*4, src + (long)c*L_ + col);
        }
        CP_COMMIT();
    };
    pref(0, img0);

    // C frags init with biases
    float C[4][4][4];
    #pragma unroll
    for (int mt = 0; mt < 4; mt++) {
        const float* bias = (mt < 2) ? bk : bv;
        int ob = (mt & 1) * 16;
        float blo = bias[ob + g], bhi = bias[ob + 8 + g];
        #pragma unroll
        for (int nt = 0; nt < 4; nt++) {
            C[mt][nt][0] = C[mt][nt][1] = blo;
            C[mt][nt][2] = C[mt][nt][3] = bhi;
        }
    }
    __syncthreads();

    int lw = w * 32;
    for (int ks = 0; ks < 4; ks++) {
        if (ks < 3) { pref(ks + 1, (ks & 1) ? img0 : img1); CP_WAIT1(); }
        else CP_WAIT0();
        __syncthreads();
        const float* I = (ks & 1) ? img1 : img0;
        #pragma unroll
        for (int kk = 0; kk < 4; kk++) {
            uint32_t A[4][4];
            #pragma unroll
            for (int mt = 0; mt < 4; mt++) {
                const uint32_t* wp = Wsm + (mt*16)*PW + ks*32 + kk*8;
                A[mt][0] = wp[ g   *PW + q];
                A[mt][1] = wp[(g+8)*PW + q];
                A[mt][2] = wp[ g   *PW + q + 4];
                A[mt][3] = wp[(g+8)*PW + q + 4];
            }
            uint32_t Bf[4][2];
            #pragma unroll
            for (int nt = 0; nt < 4; nt++) {
                int l = lw + nt*8 + g;
                const float* r0 = I + (kk*16 + 2*q    )*PI + l;
                const float* r1 = I + (kk*16 + 2*q + 8)*PI + l;
                Bf[nt][0] = pk_bf16x2(r0[PI], r0[0]);
                Bf[nt][1] = pk_bf16x2(r1[PI], r1[0]);
            }
            #pragma unroll
            for (int mt = 0; mt < 4; mt++)
                #pragma unroll
                for (int nt = 0; nt < 4; nt++)
                    mma_bf16(C[mt][nt], A[mt], Bf[nt][0], Bf[nt][1]);
        }
        __syncthreads();
    }

    // K epilogue: quad shfl-transpose -> g_Kb[l][o2]
    bool odd = (g & 1);
    int sA = 8*q + (g >> 1), sB = sA + 4;
    #pragma unroll
    for (int mt = 0; mt < 2; mt++)
        #pragma unroll
        for (int nt = 0; nt < 4; nt++) {
            float* c = C[mt][nt];
            float t0 = __shfl_sync(~0u, c[0], sA), t1 = __shfl_sync(~0u, c[1], sA);
            float t2 = __shfl_sync(~0u, c[0], sB), t3 = __shfl_sync(~0u, c[1], sB);
            float t4 = __shfl_sync(~0u, c[2], sA), t5 = __shfl_sync(~0u, c[3], sA);
            float t6 = __shfl_sync(~0u, c[2], sB), t7 = __shfl_sync(~0u, c[3], sB);
            float lo0 = odd ? t1 : t0, hi0 = odd ? t3 : t2;
            float lo1 = odd ? t5 : t4, hi1 = odd ? t7 : t6;
            long l = (long)b*L_ + l0 + lw + nt*8 + g;
            g_Kb[l*16 + mt*8 + q    ] = pk_bf16x2(hi0, lo0);
            g_Kb[l*16 + mt*8 + 4 + q] = pk_bf16x2(hi1, lo1);
        }
    // V epilogue: direct channel-major stores
    #pragma unroll
    for (int mt = 2; mt < 4; mt++)
        #pragma unroll
        for (int nt = 0; nt < 4; nt++) {
            int c = (mt - 2)*16 + g;
            long base = ((long)b*GC_ + c)*L_ + l0 + lw + nt*8 + 2*q;
            *(float2*)(g_VTc + base)         = make_float2(C[mt][nt][0], C[mt][nt][1]);
            *(float2*)(g_VTc + base + 8*L_)  = make_float2(C[mt][nt][2], C[mt][nt][3]);
        }
}

// ===========================================================================
// Kernel 3: stats (bf16 GEMM1, split exp) + V' production.
// Warp owns 32 l-rows; D[l] = sum_n exp2(s); V' = V*Dinv packed into g_Vb.
// ===========================================================================
#define QP 20

__global__ __launch_bounds__(256, 1) void k_stats_mma()
{
    __shared__ __align__(16) uint32_t Qs[2][128*QP];
    __shared__ float dinvS[256];
    int tid = threadIdx.x, w = tid >> 5, lane = tid & 31;
    int q = lane & 3, g = lane >> 2;
    int b = blockIdx.x >> 4, l0 = (blockIdx.x & 15) * 256;
    uint32_t qs_b = smem_u32(Qs);

    uint32_t A[2][2][4];
    #pragma unroll
    for (int mt = 0; mt < 2; mt++) {
        const uint32_t* kp = g_Kb + ((long)b*L_ + l0 + w*32 + mt*16)*16;
        #pragma unroll
        for (int kk = 0; kk < 2; kk++) {
            A[mt][kk][0] = kp[ g   *16 + 8*kk + q    ];
            A[mt][kk][1] = kp[(g+8)*16 + 8*kk + q    ];
            A[mt][kk][2] = kp[ g   *16 + 8*kk + q + 4];
            A[mt][kk][3] = kp[(g+8)*16 + 8*kk + q + 4];
        }
    }

    auto prefetch = [&](int nc, int buf) {
        const uint32_t* src = g_Qb + ((long)b*N_ + nc*128)*16;
        #pragma unroll
        for (int it = 0; it < 2; it++) {
            int i = tid + it*256;
            int r = i >> 2, t = i & 3;
            cp16(qs_b + (buf*128*QP + r*QP + 4*t)*4, src + r*16 + 4*t);
        }
        CP_COMMIT();
    };
    prefetch(0, 0);

    float d[2][2] = {{0.f,0.f},{0.f,0.f}};
    for (int nc = 0; nc < 32; nc++) {
        if (nc < 31) { prefetch(nc + 1, (nc + 1) & 1); CP_WAIT1(); }
        else CP_WAIT0();
        __syncthreads();
        const uint32_t* Q = &Qs[nc & 1][0];
        #pragma unroll 4
        for (int j = 0; j < 16; j++) {
            const uint32_t* bp = &Q[(g + 8*j)*QP + q];
            uint32_t b00 = bp[0], b01 = bp[4];
            uint32_t b10 = bp[8], b11 = bp[12];
            {   // mt 0: MUFU exp
                float c[4] = {0.f, 0.f, 0.f, 0.f};
                mma_bf16(c, A[0][0], b00, b01);
                mma_bf16(c, A[0][1], b10, b11);
                d[0][0] += ex2f(c[0]) + ex2f(c[1]);
                d[0][1] += ex2f(c[2]) + ex2f(c[3]);
            }
            {   // mt 1: poly exp (fma/alu pipes)
                float c[4] = {0.f, 0.f, 0.f, 0.f};
                mma_bf16(c, A[1][0], b00, b01);
                mma_bf16(c, A[1][1], b10, b11);
                d[1][0] += ex2p(c[0]) + ex2p(c[1]);
                d[1][1] += ex2p(c[2]) + ex2p(c[3]);
            }
        }
        __syncthreads();
    }
    #pragma unroll
    for (int mt = 0; mt < 2; mt++) {
        #pragma unroll
        for (int h = 0; h < 2; h++) {
            float dv = d[mt][h];
            dv += __shfl_xor_sync(~0u, dv, 1);
            dv += __shfl_xor_sync(~0u, dv, 2);
            if (q == 0) dinvS[w*32 + mt*16 + h*8 + g] = 1.0f / dv;
        }
    }
    __syncthreads();

    // V' production: channel-major read, pack pairs over l, coalesced write
    uint32_t* dst = g_Vb + ((long)b*GC_)*(L_/2) + (l0 >> 1);
    const float* vsrc = g_VTc + ((long)b*GC_)*L_ + l0;
    #pragma unroll
    for (int t = 0; t < 16; t++) {
        int u = tid + t*256;
        int c = u >> 7, l2 = u & 127;
        float2 v = *(const float2*)(vsrc + (long)c*L_ + 2*l2);
        dst[(long)c*(L_/2) + l2] =
            pk_bf16x2(v.y * dinvS[2*l2 + 1], v.x * dinvS[2*l2]);
    }
}

// ===========================================================================
// Kernel 4: final (bf16 MMAs, split exp, cp.async double buffer).
// ===========================================================================
#define KP 20
#define VP 68

__global__ __launch_bounds__(256, 1) void k_final_mma(
    const float* __restrict__ graph, const float* __restrict__ Wc,
    const float* __restrict__ bc, float* __restrict__ out)
{
    __shared__ __align__(16) uint32_t Ks[2][128*KP];
    __shared__ __align__(16) uint32_t Vbs[2][32*VP];
    __shared__ uint32_t Wb[32*17];
    int tid = threadIdx.x, w = tid >> 5, lane = tid & 31;
    int q = lane & 3, g = lane >> 2;
    int b = blockIdx.x >> 4, n0 = (blockIdx.x & 15) * 256;
    uint32_t ks_b = smem_u32(Ks), vb_b = smem_u32(Vbs);

    uint32_t A[2][2][4];
    #pragma unroll
    for (int mt = 0; mt < 2; mt++) {
        const uint32_t* qp = g_Qb + ((long)b*N_ + n0 + w*32 + mt*16)*16;
        #pragma unroll
        for (int kk = 0; kk < 2; kk++) {
            A[mt][kk][0] = qp[ g   *16 + 8*kk + q    ];
            A[mt][kk][1] = qp[(g+8)*16 + 8*kk + q    ];
            A[mt][kk][2] = qp[ g   *16 + 8*kk + q + 4];
            A[mt][kk][3] = qp[(g+8)*16 + 8*kk + q + 4];
        }
    }
    for (int i = tid; i < 32*16; i += 256) {
        int o = i >> 4, c2 = i & 15;
        Wb[o*17 + c2] = pk_bf16x2(Wc[o*32 + 2*c2 + 1], Wc[o*32 + 2*c2]);
    }

    const uint32_t* vbsrc = g_Vb + ((long)b*GC_)*(L_/2);
    auto prefetch = [&](int lc, int buf) {
        const uint32_t* ksrc = g_Kb + ((long)b*L_ + lc*128)*16;
        #pragma unroll
        for (int it = 0; it < 2; it++) {
            int i = tid + it*256;
            int r = i >> 2, t = i & 3;
            cp16(ks_b + (buf*128*KP + r*KP + 4*t)*4, ksrc + r*16 + 4*t);
        }
        #pragma unroll
        for (int it = 0; it < 2; it++) {
            int i = tid + it*256;
            int c = i >> 4, t2 = i & 15;
            cp16(vb_b + (buf*32*VP + c*VP + 4*t2)*4,
                 vbsrc + (long)c*(L_/2) + lc*64 + 4*t2);
        }
        CP_COMMIT();
    };
    prefetch(0, 0);

    float mc[2][4][4];
    #pragma unroll
    for (int mt = 0; mt < 2; mt++)
        #pragma unroll
        for (int cf = 0; cf < 4; cf++)
            #pragma unroll
            for (int x = 0; x < 4; x++) mc[mt][cf][x] = 0.f;

    for (int lc = 0; lc < 32; lc++) {
        if (lc < 31) { prefetch(lc + 1, (lc + 1) & 1); CP_WAIT1(); }
        else CP_WAIT0();
        __syncthreads();
        const uint32_t* K = &Ks[lc & 1][0];
        const uint32_t* V = &Vbs[lc & 1][0];

        #pragma unroll 2
        for (int s = 0; s < 8; s++) {
            const uint32_t* bpa = &K[(g + 16*s    )*KP + q];
            const uint32_t* bpb = &K[(g + 16*s + 8)*KP + q];
            uint32_t ba00 = bpa[0], ba01 = bpa[4], ba10 = bpa[8], ba11 = bpa[12];
            uint32_t bb00 = bpb[0], bb01 = bpb[4], bb10 = bpb[8], bb11 = bpb[12];
            uint32_t vb0[4], vb1[4];
            #pragma unroll
            for (int cf = 0; cf < 4; cf++) {
                vb0[cf] = V[(g + 8*cf)*VP + 8*s + q    ];
                vb1[cf] = V[(g + 8*cf)*VP + 8*s + q + 4];
            }
            #pragma unroll
            for (int mt = 0; mt < 2; mt++) {
                float c0[4] = {0.f,0.f,0.f,0.f};
                float c1[4] = {0.f,0.f,0.f,0.f};
                mma_bf16(c0, A[mt][0], ba00, ba01);
                mma_bf16(c0, A[mt][1], ba10, ba11);
                mma_bf16(c1, A[mt][0], bb00, bb01);
                mma_bf16(c1, A[mt][1], bb10, bb11);
                uint32_t A2[4];
                if (mt == 0) {   // MUFU half
                    A2[0] = pk_bf16x2(ex2f(c0[1]), ex2f(c0[0]));
                    A2[1] = pk_bf16x2(ex2f(c0[3]), ex2f(c0[2]));
                    A2[2] = pk_bf16x2(ex2f(c1[1]), ex2f(c1[0]));
                    A2[3] = pk_bf16x2(ex2f(c1[3]), ex2f(c1[2]));
                } else {         // poly half (fma/alu pipes)
                    A2[0] = pk_bf16x2(ex2p(c0[1]), ex2p(c0[0]));
                    A2[1] = pk_bf16x2(ex2p(c0[3]), ex2p(c0[2]));
                    A2[2] = pk_bf16x2(ex2p(c1[1]), ex2p(c1[0]));
                    A2[3] = pk_bf16x2(ex2p(c1[3]), ex2p(c1[2]));
                }
                #pragma unroll
                for (int cf = 0; cf < 4; cf++)
                    mma_bf16(mc[mt][cf], A2, vb0[cf], vb1[cf]);
            }
        }
        __syncthreads();
    }

    // Epilogue GEMM3: out = graph + bc + msg·Wcᵀ
    #pragma unroll
    for (int mt = 0; mt < 2; mt++) {
        uint32_t A3[2][4];
        #pragma unroll
        for (int t = 0; t < 2; t++) {
            A3[t][0] = pk_bf16x2(mc[mt][2*t  ][1], mc[mt][2*t  ][0]);
            A3[t][1] = pk_bf16x2(mc[mt][2*t  ][3], mc[mt][2*t  ][2]);
            A3[t][2] = pk_bf16x2(mc[mt][2*t+1][1], mc[mt][2*t+1][0]);
            A3[t][3] = pk_bf16x2(mc[mt][2*t+1][3], mc[mt][2*t+1][2]);
        }
        long nbase = (long)b*N_ + n0 + w*32 + mt*16;
        const float* gp = graph + nbase*32;
        float* op = out + nbase*32;
        #pragma unroll
        for (int of = 0; of < 4; of++) {
            int col = 8*of + 2*q;
            float bc0 = bc[col], bc1 = bc[col + 1];
            float2 gr0 = *(const float2*)(gp + g*32 + col);
            float2 gr1 = *(const float2*)(gp + (g + 8)*32 + col);
            float c[4] = { gr0.x + bc0, gr0.y + bc1, gr1.x + bc0, gr1.y + bc1 };
            #pragma unroll
            for (int t = 0; t < 2; t++) {
                uint32_t b0 = Wb[(g + 8*of)*17 + 8*t + q    ];
                uint32_t b1 = Wb[(g + 8*of)*17 + 8*t + q + 4];
                mma_bf16(c, A3[t], b0, b1);
            }
            *(float2*)(op + g*32 + col)       = make_float2(c[0], c[1]);
            *(float2*)(op + (g + 8)*32 + col) = make_float2(c[2], c[3]);
        }
    }
}

// ===========================================================================
extern "C" void kernel_launch(void* const* d_in, const int* in_sizes, int n_in,
                              void* d_out, int out_size)
{
    const float* graph = (const float*)d_in[0];
    const float* img   = (const float*)d_in[1];
    const float* Wq    = (const float*)d_in[2];
    const float* bq    = (const float*)d_in[3];
    const float* Wk    = (const float*)d_in[4];
    const float* bk    = (const float*)d_in[5];
    const float* Wv    = (const float*)d_in[6];
    const float* bv    = (const float*)d_in[7];
    const float* Wc    = (const float*)d_in[8];
    const float* bc    = (const float*)d_in[9];
    float* out = (float*)d_out;

    size_t proj_smem = (64*PW + 2*64*PI) * sizeof(uint32_t);
    static int attr_set = 0;
    if (!attr_set) {
        cudaFuncSetAttribute(k_proj_kv_mma,
                             cudaFuncAttributeMaxDynamicSharedMemorySize,
                             (int)proj_smem);
        attr_set = 1;
    }

    k_proj_q     <<<B_*(N_/64), 256>>>(graph, Wq, bq);
    k_proj_kv_mma<<<B_*(L_/256), 256, proj_smem>>>(img, Wk, bk, Wv, bv);
    k_stats_mma  <<<B_*(L_/256), 256>>>();
    k_final_mma  <<<B_*(N_/256), 256>>>(graph, Wc, bc, out);
}

// round 7
// speedup vs baseline: 8.3117x; 1.2123x over previous
#include <cuda_runtime.h>
#include <cstdint>

#define B_  8
#define N_  4096
#define L_  4096
#define GC_ 32
#define IC_ 256

__device__ uint32_t g_Qb [B_*N_*16];      // [b][n][k2] bf16x2 (Q*QSCALE)
__device__ uint32_t g_Kb [B_*L_*16];      // [b][l][k2] bf16x2
__device__ float    g_VTc[B_*GC_*L_];     // [b][c][l] raw f32 (channel-major)
__device__ uint32_t g_Vb [B_*GC_*(L_/2)]; // [b][c][l2] bf16x2 of V*Dinv

#define QSCALE 0.2550668292560464f  // (1/sqrt(32)) * log2(e)

// ===========================================================================
// helpers
// ===========================================================================
__device__ __forceinline__ uint32_t smem_u32(const void* p) {
    uint32_t a;
    asm("{ .reg .u64 t; cvta.to.shared.u64 t, %1; cvt.u32.u64 %0, t; }"
        : "=r"(a) : "l"(p));
    return a;
}
__device__ __forceinline__ float ex2f(float x) {
    float y;
    asm("ex2.approx.f32 %0, %1;" : "=f"(y) : "f"(x));
    return y;
}
__device__ __forceinline__ uint32_t pk_bf16x2(float hi, float lo) {
    uint32_t r;
    asm("cvt.rn.bf16x2.f32 %0, %1, %2;" : "=r"(r) : "f"(hi), "f"(lo));
    return r;
}
__device__ __forceinline__ void mma_bf16(float c[4], const uint32_t a[4],
                                         uint32_t b0, uint32_t b1) {
    asm volatile("mma.sync.aligned.m16n8k16.row.col.f32.bf16.bf16.f32 "
        "{%0,%1,%2,%3}, {%4,%5,%6,%7}, {%8,%9}, {%0,%1,%2,%3};"
        : "+f"(c[0]), "+f"(c[1]), "+f"(c[2]), "+f"(c[3])
        : "r"(a[0]), "r"(a[1]), "r"(a[2]), "r"(a[3]), "r"(b0), "r"(b1));
}
__device__ __forceinline__ void cp16(uint32_t s, const void* g) {
    asm volatile("cp.async.ca.shared.global [%0], [%1], 16;"
                 :: "r"(s), "l"(g) : "memory");
}
#define CP_COMMIT() asm volatile("cp.async.commit_group;" ::: "memory")
#define CP_WAIT1()  asm volatile("cp.async.wait_group 1;" ::: "memory")
#define CP_WAIT0()  asm volatile("cp.async.wait_group 0;" ::: "memory")

// ===========================================================================
// Kernel 1: Q projection (SIMT, tiny) -> packed bf16x2, QSCALE folded
// ===========================================================================
__global__ __launch_bounds__(256) void k_proj_q(
    const float* __restrict__ graph, const float* __restrict__ Wq,
    const float* __restrict__ bq)
{
    __shared__ float WqS[GC_*33];
    __shared__ float gS[64*GC_];
    int b  = blockIdx.x >> 6;
    int n0 = (blockIdx.x & 63) * 64;
    int tid = threadIdx.x;

    for (int i = tid; i < GC_*GC_; i += 256)
        WqS[(i>>5)*33 + (i&31)] = Wq[i];
    const float* gp = graph + ((long)b*N_ + n0)*GC_;
    for (int i = tid; i < 64*GC_; i += 256) gS[i] = gp[i];
    __syncthreads();

    int o2 = tid & 15, nb = tid >> 4;
    float b0 = bq[2*o2], b1 = bq[2*o2 + 1];
    #pragma unroll
    for (int j = 0; j < 4; j++) {
        int n = nb + 16*j;
        float a0 = b0, a1 = b1;
        #pragma unroll
        for (int c = 0; c < 32; c++) {
            float gv = gS[n*32 + c];
            a0 += WqS[(2*o2    )*33 + c] * gv;
            a1 += WqS[(2*o2 + 1)*33 + c] * gv;
        }
        g_Qb[((long)b*N_ + n0 + n)*16 + o2] = pk_bf16x2(a1*QSCALE, a0*QSCALE);
    }
}

// ===========================================================================
// Kernel 2: K/V projection via bf16 MMA.
// A = [Wk;Wv] (64x256), B = img tile (256 l per CTA), C[64 o][256 l].
// K: shfl-transpose -> g_Kb[l][o2] bf16x2.  V: direct -> g_VTc[c][l] f32.
// ===========================================================================
#define PW 132   // W smem pitch (words)
#define PI 260   // img smem pitch (f32 words)

__global__ __launch_bounds__(256, 1) void k_proj_kv_mma(
    const float* __restrict__ img,
    const float* __restrict__ Wk, const float* __restrict__ bk,
    const float* __restrict__ Wv, const float* __restrict__ bv)
{
    extern __shared__ uint32_t shm[];
    uint32_t* Wsm  = shm;                       // [64][PW]
    float*    img0 = (float*)(shm + 64*PW);     // [64][PI] x2 buffers
    float*    img1 = img0 + 64*PI;

    int tid = threadIdx.x, w = tid >> 5, lane = tid & 31;
    int q = lane & 3, g = lane >> 2;
    int b = blockIdx.x >> 4, l0 = (blockIdx.x & 15) * 256;

    #pragma unroll
    for (int t = 0; t < 32; t++) {
        int u = tid + t*256;
        int o = u >> 7, c2 = u & 127;
        const float* src = (o < 32) ? (Wk + o*IC_ + 2*c2) : (Wv + (o-32)*IC_ + 2*c2);
        float2 v = *(const float2*)src;
        Wsm[o*PW + c2] = pk_bf16x2(v.y, v.x);
    }

    auto pref = [&](int ks, float* dstbuf) {
        const float* src = img + ((long)b*IC_ + ks*64)*L_ + l0;
        uint32_t dstb = smem_u32(dstbuf);
        #pragma unroll
        for (int t = 0; t < 16; t++) {
            int u = tid + t*256;
            int c = u >> 6, col = (u & 63) * 4;
            cp16(dstb + (c*PI + col)*4, src + (long)c*L_ + col);
        }
        CP_COMMIT();
    };
    pref(0, img0);

    float C[4][4][4];
    #pragma unroll
    for (int mt = 0; mt < 4; mt++) {
        const float* bias = (mt < 2) ? bk : bv;
        int ob = (mt & 1) * 16;
        float blo = bias[ob + g], bhi = bias[ob + 8 + g];
        #pragma unroll
        for (int nt = 0; nt < 4; nt++) {
            C[mt][nt][0] = C[mt][nt][1] = blo;
            C[mt][nt][2] = C[mt][nt][3] = bhi;
        }
    }
    __syncthreads();

    int lw = w * 32;
    for (int ks = 0; ks < 4; ks++) {
        if (ks < 3) { pref(ks + 1, (ks & 1) ? img0 : img1); CP_WAIT1(); }
        else CP_WAIT0();
        __syncthreads();
        const float* I = (ks & 1) ? img1 : img0;
        #pragma unroll
        for (int kk = 0; kk < 4; kk++) {
            uint32_t A[4][4];
            #pragma unroll
            for (int mt = 0; mt < 4; mt++) {
                const uint32_t* wp = Wsm + (mt*16)*PW + ks*32 + kk*8;
                A[mt][0] = wp[ g   *PW + q];
                A[mt][1] = wp[(g+8)*PW + q];
                A[mt][2] = wp[ g   *PW + q + 4];
                A[mt][3] = wp[(g+8)*PW + q + 4];
            }
            uint32_t Bf[4][2];
            #pragma unroll
            for (int nt = 0; nt < 4; nt++) {
                int l = lw + nt*8 + g;
                const float* r0 = I + (kk*16 + 2*q    )*PI + l;
                const float* r1 = I + (kk*16 + 2*q + 8)*PI + l;
                Bf[nt][0] = pk_bf16x2(r0[PI], r0[0]);
                Bf[nt][1] = pk_bf16x2(r1[PI], r1[0]);
            }
            #pragma unroll
            for (int mt = 0; mt < 4; mt++)
                #pragma unroll
                for (int nt = 0; nt < 4; nt++)
                    mma_bf16(C[mt][nt], A[mt], Bf[nt][0], Bf[nt][1]);
        }
        __syncthreads();
    }

    // K epilogue: quad shfl-transpose -> g_Kb[l][o2]
    bool odd = (g & 1);
    int sA = 8*q + (g >> 1), sB = sA + 4;
    #pragma unroll
    for (int mt = 0; mt < 2; mt++)
        #pragma unroll
        for (int nt = 0; nt < 4; nt++) {
            float* c = C[mt][nt];
            float t0 = __shfl_sync(~0u, c[0], sA), t1 = __shfl_sync(~0u, c[1], sA);
            float t2 = __shfl_sync(~0u, c[0], sB), t3 = __shfl_sync(~0u, c[1], sB);
            float t4 = __shfl_sync(~0u, c[2], sA), t5 = __shfl_sync(~0u, c[3], sA);
            float t6 = __shfl_sync(~0u, c[2], sB), t7 = __shfl_sync(~0u, c[3], sB);
            float lo0 = odd ? t1 : t0, hi0 = odd ? t3 : t2;
            float lo1 = odd ? t5 : t4, hi1 = odd ? t7 : t6;
            long l = (long)b*L_ + l0 + lw + nt*8 + g;
            g_Kb[l*16 + mt*8 + q    ] = pk_bf16x2(hi0, lo0);
            g_Kb[l*16 + mt*8 + 4 + q] = pk_bf16x2(hi1, lo1);
        }
    // V epilogue: direct channel-major stores
    #pragma unroll
    for (int mt = 2; mt < 4; mt++)
        #pragma unroll
        for (int nt = 0; nt < 4; nt++) {
            int c = (mt - 2)*16 + g;
            long base = ((long)b*GC_ + c)*L_ + l0 + lw + nt*8 + 2*q;
            *(float2*)(g_VTc + base)         = make_float2(C[mt][nt][0], C[mt][nt][1]);
            *(float2*)(g_VTc + base + 8*L_)  = make_float2(C[mt][nt][2], C[mt][nt][3]);
        }
}

// ===========================================================================
// Kernel 3: stats (bf16 GEMM1, pure MUFU exp) + V' production.
// ===========================================================================
#define QP 20

__global__ __launch_bounds__(256, 1) void k_stats_mma()
{
    __shared__ __align__(16) uint32_t Qs[2][128*QP];
    __shared__ float dinvS[256];
    int tid = threadIdx.x, w = tid >> 5, lane = tid & 31;
    int q = lane & 3, g = lane >> 2;
    int b = blockIdx.x >> 4, l0 = (blockIdx.x & 15) * 256;
    uint32_t qs_b = smem_u32(Qs);

    uint32_t A[2][2][4];
    #pragma unroll
    for (int mt = 0; mt < 2; mt++) {
        const uint32_t* kp = g_Kb + ((long)b*L_ + l0 + w*32 + mt*16)*16;
        #pragma unroll
        for (int kk = 0; kk < 2; kk++) {
            A[mt][kk][0] = kp[ g   *16 + 8*kk + q    ];
            A[mt][kk][1] = kp[(g+8)*16 + 8*kk + q    ];
            A[mt][kk][2] = kp[ g   *16 + 8*kk + q + 4];
            A[mt][kk][3] = kp[(g+8)*16 + 8*kk + q + 4];
        }
    }

    auto prefetch = [&](int nc, int buf) {
        const uint32_t* src = g_Qb + ((long)b*N_ + nc*128)*16;
        #pragma unroll
        for (int it = 0; it < 2; it++) {
            int i = tid + it*256;
            int r = i >> 2, t = i & 3;
            cp16(qs_b + (buf*128*QP + r*QP + 4*t)*4, src + r*16 + 4*t);
        }
        CP_COMMIT();
    };
    prefetch(0, 0);

    float d[2][2] = {{0.f,0.f},{0.f,0.f}};
    for (int nc = 0; nc < 32; nc++) {
        if (nc < 31) { prefetch(nc + 1, (nc + 1) & 1); CP_WAIT1(); }
        else CP_WAIT0();
        __syncthreads();
        const uint32_t* Q = &Qs[nc & 1][0];
        #pragma unroll 4
        for (int j = 0; j < 16; j++) {
            const uint32_t* bp = &Q[(g + 8*j)*QP + q];
            uint32_t b00 = bp[0], b01 = bp[4];
            uint32_t b10 = bp[8], b11 = bp[12];
            #pragma unroll
            for (int mt = 0; mt < 2; mt++) {
                float c[4] = {0.f, 0.f, 0.f, 0.f};
                mma_bf16(c, A[mt][0], b00, b01);
                mma_bf16(c, A[mt][1], b10, b11);
                d[mt][0] += ex2f(c[0]) + ex2f(c[1]);
                d[mt][1] += ex2f(c[2]) + ex2f(c[3]);
            }
        }
        __syncthreads();
    }
    #pragma unroll
    for (int mt = 0; mt < 2; mt++) {
        #pragma unroll
        for (int h = 0; h < 2; h++) {
            float dv = d[mt][h];
            dv += __shfl_xor_sync(~0u, dv, 1);
            dv += __shfl_xor_sync(~0u, dv, 2);
            if (q == 0) dinvS[w*32 + mt*16 + h*8 + g] = 1.0f / dv;
        }
    }
    __syncthreads();

    // V' production: channel-major read, pack pairs over l, coalesced write
    uint32_t* dst = g_Vb + ((long)b*GC_)*(L_/2) + (l0 >> 1);
    const float* vsrc = g_VTc + ((long)b*GC_)*L_ + l0;
    #pragma unroll
    for (int t = 0; t < 16; t++) {
        int u = tid + t*256;
        int c = u >> 7, l2 = u & 127;
        float2 v = *(const float2*)(vsrc + (long)c*L_ + 2*l2);
        dst[(long)c*(L_/2) + l2] =
            pk_bf16x2(v.y * dinvS[2*l2 + 1], v.x * dinvS[2*l2]);
    }
}

// ===========================================================================
// Kernel 4: final (bf16 MMAs, pure MUFU exp, cp.async double buffer).
// ===========================================================================
#define KP 20
#define VP 68

__global__ __launch_bounds__(256, 1) void k_final_mma(
    const float* __restrict__ graph, const float* __restrict__ Wc,
    const float* __restrict__ bc, float* __restrict__ out)
{
    __shared__ __align__(16) uint32_t Ks[2][128*KP];
    __shared__ __align__(16) uint32_t Vbs[2][32*VP];
    __shared__ uint32_t Wb[32*17];
    int tid = threadIdx.x, w = tid >> 5, lane = tid & 31;
    int q = lane & 3, g = lane >> 2;
    int b = blockIdx.x >> 4, n0 = (blockIdx.x & 15) * 256;
    uint32_t ks_b = smem_u32(Ks), vb_b = smem_u32(Vbs);

    uint32_t A[2][2][4];
    #pragma unroll
    for (int mt = 0; mt < 2; mt++) {
        const uint32_t* qp = g_Qb + ((long)b*N_ + n0 + w*32 + mt*16)*16;
        #pragma unroll
        for (int kk = 0; kk < 2; kk++) {
            A[mt][kk][0] = qp[ g   *16 + 8*kk + q    ];
            A[mt][kk][1] = qp[(g+8)*16 + 8*kk + q    ];
            A[mt][kk][2] = qp[ g   *16 + 8*kk + q + 4];
            A[mt][kk][3] = qp[(g+8)*16 + 8*kk + q + 4];
        }
    }
    for (int i = tid; i < 32*16; i += 256) {
        int o = i >> 4, c2 = i & 15;
        Wb[o*17 + c2] = pk_bf16x2(Wc[o*32 + 2*c2 + 1], Wc[o*32 + 2*c2]);
    }

    const uint32_t* vbsrc = g_Vb + ((long)b*GC_)*(L_/2);
    auto prefetch = [&](int lc, int buf) {
        const uint32_t* ksrc = g_Kb + ((long)b*L_ + lc*128)*16;
        #pragma unroll
        for (int it = 0; it < 2; it++) {
            int i = tid + it*256;
            int r = i >> 2, t = i & 3;
            cp16(ks_b + (buf*128*KP + r*KP + 4*t)*4, ksrc + r*16 + 4*t);
        }
        #pragma unroll
        for (int it = 0; it < 2; it++) {
            int i = tid + it*256;
            int c = i >> 4, t2 = i & 15;
            cp16(vb_b + (buf*32*VP + c*VP + 4*t2)*4,
                 vbsrc + (long)c*(L_/2) + lc*64 + 4*t2);
        }
        CP_COMMIT();
    };
    prefetch(0, 0);

    float mc[2][4][4];
    #pragma unroll
    for (int mt = 0; mt < 2; mt++)
        #pragma unroll
        for (int cf = 0; cf < 4; cf++)
            #pragma unroll
            for (int x = 0; x < 4; x++) mc[mt][cf][x] = 0.f;

    for (int lc = 0; lc < 32; lc++) {
        if (lc < 31) { prefetch(lc + 1, (lc + 1) & 1); CP_WAIT1(); }
        else CP_WAIT0();
        __syncthreads();
        const uint32_t* K = &Ks[lc & 1][0];
        const uint32_t* V = &Vbs[lc & 1][0];

        #pragma unroll 2
        for (int s = 0; s < 8; s++) {
            const uint32_t* bpa = &K[(g + 16*s    )*KP + q];
            const uint32_t* bpb = &K[(g + 16*s + 8)*KP + q];
            uint32_t ba00 = bpa[0], ba01 = bpa[4], ba10 = bpa[8], ba11 = bpa[12];
            uint32_t bb00 = bpb[0], bb01 = bpb[4], bb10 = bpb[8], bb11 = bpb[12];
            uint32_t vb0[4], vb1[4];
            #pragma unroll
            for (int cf = 0; cf < 4; cf++) {
                vb0[cf] = V[(g + 8*cf)*VP + 8*s + q    ];
                vb1[cf] = V[(g + 8*cf)*VP + 8*s + q + 4];
            }
            #pragma unroll
            for (int mt = 0; mt < 2; mt++) {
                float c0[4] = {0.f,0.f,0.f,0.f};
                float c1[4] = {0.f,0.f,0.f,0.f};
                mma_bf16(c0, A[mt][0], ba00, ba01);
                mma_bf16(c0, A[mt][1], ba10, ba11);
                mma_bf16(c1, A[mt][0], bb00, bb01);
                mma_bf16(c1, A[mt][1], bb10, bb11);
                uint32_t A2[4];
                A2[0] = pk_bf16x2(ex2f(c0[1]), ex2f(c0[0]));
                A2[1] = pk_bf16x2(ex2f(c0[3]), ex2f(c0[2]));
                A2[2] = pk_bf16x2(ex2f(c1[1]), ex2f(c1[0]));
                A2[3] = pk_bf16x2(ex2f(c1[3]), ex2f(c1[2]));
                #pragma unroll
                for (int cf = 0; cf < 4; cf++)
                    mma_bf16(mc[mt][cf], A2, vb0[cf], vb1[cf]);
            }
        }
        __syncthreads();
    }

    // Epilogue GEMM3: out = graph + bc + msg·Wcᵀ
    #pragma unroll
    for (int mt = 0; mt < 2; mt++) {
        uint32_t A3[2][4];
        #pragma unroll
        for (int t = 0; t < 2; t++) {
            A3[t][0] = pk_bf16x2(mc[mt][2*t  ][1], mc[mt][2*t  ][0]);
            A3[t][1] = pk_bf16x2(mc[mt][2*t  ][3], mc[mt][2*t  ][2]);
            A3[t][2] = pk_bf16x2(mc[mt][2*t+1][1], mc[mt][2*t+1][0]);
            A3[t][3] = pk_bf16x2(mc[mt][2*t+1][3], mc[mt][2*t+1][2]);
        }
        long nbase = (long)b*N_ + n0 + w*32 + mt*16;
        const float* gp = graph + nbase*32;
        float* op = out + nbase*32;
        #pragma unroll
        for (int of = 0; of < 4; of++) {
            int col = 8*of + 2*q;
            float bc0 = bc[col], bc1 = bc[col + 1];
            float2 gr0 = *(const float2*)(gp + g*32 + col);
            float2 gr1 = *(const float2*)(gp + (g + 8)*32 + col);
            float c[4] = { gr0.x + bc0, gr0.y + bc1, gr1.x + bc0, gr1.y + bc1 };
            #pragma unroll
            for (int t = 0; t < 2; t++) {
                uint32_t b0 = Wb[(g + 8*of)*17 + 8*t + q    ];
                uint32_t b1 = Wb[(g + 8*of)*17 + 8*t + q + 4];
                mma_bf16(c, A3[t], b0, b1);
            }
            *(float2*)(op + g*32 + col)       = make_float2(c[0], c[1]);
            *(float2*)(op + (g + 8)*32 + col) = make_float2(c[2], c[3]);
        }
    }
}

// ===========================================================================
extern "C" void kernel_launch(void* const* d_in, const int* in_sizes, int n_in,
                              void* d_out, int out_size)
{
    const float* graph = (const float*)d_in[0];
    const float* img   = (const float*)d_in[1];
    const float* Wq    = (const float*)d_in[2];
    const float* bq    = (const float*)d_in[3];
    const float* Wk    = (const float*)d_in[4];
    const float* bk    = (const float*)d_in[5];
    const float* Wv    = (const float*)d_in[6];
    const float* bv    = (const float*)d_in[7];
    const float* Wc    = (const float*)d_in[8];
    const float* bc    = (const float*)d_in[9];
    float* out = (float*)d_out;

    size_t proj_smem = (64*PW + 2*64*PI) * sizeof(uint32_t);
    static int attr_set = 0;
    if (!attr_set) {
        cudaFuncSetAttribute(k_proj_kv_mma,
                             cudaFuncAttributeMaxDynamicSharedMemorySize,
                             (int)proj_smem);
        attr_set = 1;
    }

    k_proj_q     <<<B_*(N_/64), 256>>>(graph, Wq, bq);
    k_proj_kv_mma<<<B_*(L_/256), 256, proj_smem>>>(img, Wk, bk, Wv, bv);
    k_stats_mma  <<<B_*(L_/256), 256>>>();
    k_final_mma  <<<B_*(N_/256), 256>>>(graph, Wc, bc, out);
}